// round 13
// baseline (speedup 1.0000x reference)
#include <cuda_runtime.h>
#include <cuda_bf16.h>
#include <math.h>
#include <stdint.h>

#define BB     4096
#define LATENT 128
#define HH     256
#define G4     1024   // 4*HH
#define OUTN   88
#define TT     64
#define LL     5

// ---------------- static device scratch (no allocations allowed) -------------
__device__ float    g_c[LL * BB * HH];
__device__ float    g_xp[BB * HH];
__device__ float    g_gx0[BB * G4];              // layer-0 input gates (const over t)
__device__ float    g_ys[BB * TT * HH];          // [B][T][H] fp32
__device__ uint32_t g_hb32[LL * 2 * BB * HH / 2];   // h state, bf16 pairs, parity buffered
__device__ uint32_t g_wib32[LL * G4 * HH / 2];      // wih in bf16 pairs
__device__ uint32_t g_whb32[LL * G4 * HH / 2];      // whh in bf16 pairs
__device__ int      g_flags[LL * TT * 32];          // per (cell, m-block) completion (0..4)

// ---------------------------------------------------------------------------
__global__ void zero_kernel(float* __restrict__ p, int n) {
    int i = blockIdx.x * blockDim.x + threadIdx.x;
    int stride = gridDim.x * blockDim.x;
    for (; i < n; i += stride) p[i] = 0.0f;
}

// fp32 -> packed bf16x2 conversion (n2 = number of OUTPUT words)
__global__ void f2bf_kernel(const float* __restrict__ in, uint32_t* __restrict__ out, int n2) {
    int i = blockIdx.x * blockDim.x + threadIdx.x;
    int stride = gridDim.x * blockDim.x;
    for (; i < n2; i += stride) {
        uint32_t lo = (uint32_t)__bfloat16_as_ushort(__float2bfloat16_rn(in[2 * i]));
        uint32_t hi = (uint32_t)__bfloat16_as_ushort(__float2bfloat16_rn(in[2 * i + 1]));
        out[i] = lo | (hi << 16);
    }
}

__device__ __forceinline__ float sigf(float x) { return 1.0f / (1.0f + __expf(-x)); }
__device__ __forceinline__ float tanh_fast(float x) {
    float t = __expf(-2.0f * fabsf(x));
    float r = (1.0f - t) / (1.0f + t);
    return copysignf(r, x);
}
__device__ __forceinline__ void mma16(float* d, const uint32_t* a, uint32_t b0, uint32_t b1) {
    asm volatile(
        "mma.sync.aligned.m16n8k16.row.col.f32.bf16.bf16.f32 "
        "{%0,%1,%2,%3},{%4,%5,%6,%7},{%8,%9},{%0,%1,%2,%3};"
        : "+f"(d[0]), "+f"(d[1]), "+f"(d[2]), "+f"(d[3])
        : "r"(a[0]), "r"(a[1]), "r"(a[2]), "r"(a[3]), "r"(b0), "r"(b1));
}
__device__ __forceinline__ void ldm4(uint32_t* r, uint32_t addr) {
    asm volatile("ldmatrix.sync.aligned.m8n8.x4.shared.b16 {%0,%1,%2,%3}, [%4];"
                 : "=r"(r[0]), "=r"(r[1]), "=r"(r[2]), "=r"(r[3]) : "r"(addr));
}
__device__ __forceinline__ uint32_t smem_u32(const void* p) {
    uint32_t a;
    asm("{ .reg .u64 t; cvta.to.shared.u64 t, %1; cvt.u32.u64 %0, t; }" : "=r"(a) : "l"(p));
    return a;
}
__device__ __forceinline__ void cpasync16(uint32_t dst, const void* src) {
    asm volatile("cp.async.cg.shared.global [%0], [%1], 16;" :: "r"(dst), "l"(src) : "memory");
}
#define CP_COMMIT() asm volatile("cp.async.commit_group;" ::: "memory")
#define CP_WAIT1()  asm volatile("cp.async.wait_group 1;" ::: "memory")

__device__ __forceinline__ void spin_flag(const int* p) {
    int v;
    for (;;) {
        asm volatile("ld.acquire.gpu.global.b32 %0, [%1];" : "=r"(v) : "l"(p) : "memory");
        if (v >= 4) return;
        __nanosleep(64);
    }
}
__device__ __forceinline__ void bump_flag(int* p) {
    asm volatile("red.release.gpu.global.add.s32 [%0], %1;" :: "l"(p), "r"(1) : "memory");
}

// ---------------------------------------------------------------------------
// Persistent wavefront bf16 mma.sync LSTM. ONE kernel for all 320 cells.
// Grid = #SMs (1 CTA/SM, all resident). CTAs walk tiles in diagonal order,
// strided by gridDim. Per-tile readiness via per-(cell, m-block) flags:
//   RAW:  flag[l-1][t][m]==4, flag[l][t-1][m]==4
//   WAR:  flag[l+1][t-2][m]==4 (last reader of the h parity slot we overwrite)
// All deps are earlier diagonals -> acyclic -> deadlock-free with residency.
// Tile body identical to R12: 128x256 CTA tile, 16 warps (4m x 4n), m16n8k16,
// ldmatrix.x4 fragments, KT=64 stages, 3 smem buffers, one barrier per stage.
// ---------------------------------------------------------------------------
#define KT          64
#define RSW         36                 // row stride in words (32 data + 4 pad)
#define AROWS       128
#define BROWS       256
#define STAGE_WORDS ((AROWS + BROWS) * RSW)   // 13824 words = 55296 B
#define AOFFW       0
#define BOFFW       (AROWS * RSW)      // 4608
#define NSTAGE      3
#define GSTRIDE     258                // epilogue gate buffer row stride (floats)
#define SM_WORDS    (NSTAGE * STAGE_WORDS)    // 41472 words = 165888 B
#define SM_BYTES    (SM_WORDS * 4)

__global__ __launch_bounds__(512, 1) void cell_persist_kernel(
    const float* __restrict__ bih_g, const float* __restrict__ bhh_g)
{
    extern __shared__ uint32_t sm[];
    const uint32_t sbase = smem_u32(sm);
    const int tid = threadIdx.x;
    const int wid = tid >> 5, lane = tid & 31;
    const int grp = lane >> 2, tig = lane & 3;
    const int wm = wid & 3, wn = wid >> 2;

    const int q = lane >> 3, rlane = lane & 7;
    const int ldm_row = rlane + (q & 1) * 8;
    const int ldm_colw = (q >> 1) * 4;

    const size_t lsz = (size_t)BB * HH;
    const __nv_bfloat16* hb = reinterpret_cast<const __nv_bfloat16*>(g_hb32);
    __nv_bfloat16* hbw = reinterpret_cast<__nv_bfloat16*>(g_hb32);
    const __nv_bfloat16* wib = reinterpret_cast<const __nv_bfloat16*>(g_wib32);
    const __nv_bfloat16* whb = reinterpret_cast<const __nv_bfloat16*>(g_whb32);
    float* smf = reinterpret_cast<float*>(sm);

    for (int k = 0; k < TT + LL - 1; ++k) {
        int lmin = k - (TT - 1); if (lmin < 0) lmin = 0;
        int lmax = k;            if (lmax > LL - 1) lmax = LL - 1;
        const int ntiles = (lmax - lmin + 1) * 128;

        for (int i = blockIdx.x; i < ntiles; i += gridDim.x) {
            const int z = i >> 7, rem = i & 127;
            const int l = lmin + z;
            const int t = k - l;
            const int n0 = (rem & 3) * 64;
            const int mblk = rem >> 2;
            const int m0 = mblk * 128;

            // ---- wait for producers (and WAR reader) ----
            if (tid == 0) {
                if (l > 0)                    spin_flag(&g_flags[((l - 1) * TT + t) * 32 + mblk]);
                if (t > 0)                    spin_flag(&g_flags[(l * TT + (t - 1)) * 32 + mblk]);
                if (l < LL - 1 && t >= 2)     spin_flag(&g_flags[((l + 1) * TT + (t - 2)) * 32 + mblk]);
            }
            __syncthreads();

            // ---- derive operands ----
            const __nv_bfloat16* h_prev = hb + (size_t)(l * 2 + ((t + 1) & 1)) * lsz;
            __nv_bfloat16*       h_o    = hbw + (size_t)(l * 2 + (t & 1)) * lsz;
            float*               cst    = g_c + (size_t)l * lsz;
            float*               ys     = (l == LL - 1) ? (g_ys + (size_t)t * HH) : nullptr;

            const __nv_bfloat16 *A0, *W0, *A1, *W1;
            const float *bih, *gx0;
            int nst;
            const float* bhh = bhh_g + l * G4;
            if (l == 0) {
                A0 = h_prev; W0 = whb; A1 = nullptr; W1 = nullptr;
                nst = 4; bih = nullptr; gx0 = g_gx0;
            } else {
                A0 = hb + (size_t)((l - 1) * 2 + (t & 1)) * lsz;
                W0 = wib + (size_t)l * G4 * HH;
                A1 = h_prev;
                W1 = whb + (size_t)l * G4 * HH;
                nst = 8; bih = bih_g + l * G4; gx0 = nullptr;
            }
            const int half = 4;

            float acc[2][8][4] = {};

            auto load_stage = [&](int s, int buf) {
                const __nv_bfloat16* A = A0; const __nv_bfloat16* W = W0; int kt = s * KT;
                if (s >= half) { A = A1; W = W1; kt = (s - half) * KT; }
                const uint32_t base = sbase + (uint32_t)buf * (STAGE_WORDS * 4);
#pragma unroll
                for (int j = 0; j < 2; j++) {
                    int c = j * 512 + tid;
                    int r = c >> 3, sub = c & 7;
                    cpasync16(base + (AOFFW + r * RSW + sub * 4) * 4,
                              A + (size_t)(m0 + r) * HH + kt + sub * 8);
                }
#pragma unroll
                for (int j = 0; j < 4; j++) {
                    int c = j * 512 + tid;
                    int r = c >> 3, sub = c & 7;
                    int wrow = (r >> 6) * HH + n0 + (r & 63);
                    cpasync16(base + (BOFFW + r * RSW + sub * 4) * 4,
                              W + (size_t)wrow * HH + kt + sub * 8);
                }
            };

            auto compute = [&](int buf) {
                const uint32_t sa = sbase + (uint32_t)buf * (STAGE_WORDS * 4) + AOFFW * 4;
                const uint32_t sb = sbase + (uint32_t)buf * (STAGE_WORDS * 4) + BOFFW * 4;
#pragma unroll
                for (int kk = 0; kk < 4; kk++) {
                    const int k0 = kk * 8;
                    uint32_t af[2][4];
#pragma unroll
                    for (int mt = 0; mt < 2; mt++) {
                        int ra = wm * 32 + mt * 16;
                        ldm4(af[mt], sa + ((ra + ldm_row) * RSW + k0 + ldm_colw) * 4);
                    }
                    uint32_t bf[8][2];
#pragma unroll
                    for (int ntp = 0; ntp < 4; ntp++) {
                        int rb = wn * 64 + ntp * 16;
                        uint32_t r4[4];
                        ldm4(r4, sb + ((rb + ldm_row) * RSW + k0 + ldm_colw) * 4);
                        bf[2 * ntp][0] = r4[0]; bf[2 * ntp + 1][0] = r4[1];
                        bf[2 * ntp][1] = r4[2]; bf[2 * ntp + 1][1] = r4[3];
                    }
#pragma unroll
                    for (int nt = 0; nt < 8; nt++)
#pragma unroll
                        for (int mt = 0; mt < 2; mt++)
                            mma16(acc[mt][nt], af[mt], bf[nt][0], bf[nt][1]);
                }
            };

            // ---- pipeline: 2 ahead, 3 buffers, one barrier per stage ----
            load_stage(0, 0); CP_COMMIT();
            load_stage(1, 1); CP_COMMIT();
            for (int s = 0; s < nst; s++) {
                CP_WAIT1();
                __syncthreads();
                if (s + 2 < nst) load_stage(s + 2, (s + 2) % NSTAGE);
                CP_COMMIT();
                compute(s % NSTAGE);
            }
            __syncthreads();               // staging -> gate-buffer reuse

            // ---- gate pre-activations to smem ----
#pragma unroll
            for (int mt = 0; mt < 2; mt++) {
#pragma unroll
                for (int nt = 0; nt < 8; nt++) {
                    int row = wm * 32 + mt * 16 + grp;
                    int col = wn * 64 + nt * 8 + 2 * tig;
                    *reinterpret_cast<float2*>(&smf[row * GSTRIDE + col]) =
                        make_float2(acc[mt][nt][0], acc[mt][nt][1]);
                    *reinterpret_cast<float2*>(&smf[(row + 8) * GSTRIDE + col]) =
                        make_float2(acc[mt][nt][2], acc[mt][nt][3]);
                }
            }
            __syncthreads();

            // ---- epilogue: LSTM cell, coalesced global I/O ----
            const int u = tid & 63;
            const int n = n0 + u;
            const int bloc0 = (tid >> 6) * 16;

            float bsum[4];
#pragma unroll
            for (int gg = 0; gg < 4; gg++) {
                float v = bhh[gg * HH + n];
                if (bih) v += bih[gg * HH + n];
                bsum[gg] = v;
            }

            uint16_t* h_o16 = reinterpret_cast<uint16_t*>(h_o);
            for (int j = 0; j < 16; j++) {
                const int bl = bloc0 + j;
                const int gb = m0 + bl;
                float pre[4];
#pragma unroll
                for (int gg = 0; gg < 4; gg++)
                    pre[gg] = smf[bl * GSTRIDE + gg * 64 + u] + bsum[gg];
                if (gx0) {
#pragma unroll
                    for (int gg = 0; gg < 4; gg++)
                        pre[gg] += gx0[(size_t)gb * G4 + gg * HH + n];
                }
                float co = cst[(size_t)gb * HH + n];
                float iv = sigf(pre[0]);
                float fv = sigf(pre[1]);
                float gv = tanh_fast(pre[2]);
                float ov = sigf(pre[3]);
                float cn = fv * co + iv * gv;
                float hn = ov * tanh_fast(cn);
                cst[(size_t)gb * HH + n] = cn;
                h_o16[(size_t)gb * HH + n] = __bfloat16_as_ushort(__float2bfloat16_rn(hn));
                if (ys) ys[(size_t)gb * (TT * HH) + n] = hn;
            }

            // ---- publish ----
            __threadfence();
            __syncthreads();
            if (tid == 0) bump_flag(&g_flags[(l * TT + t) * 32 + mblk]);
        }
    }
}

// ---------------------------------------------------------------------------
// SIMT GEMM (small projections + output GEMM)
template <bool SIG>
__global__ __launch_bounds__(256) void gemm_bias_kernel(
    const float* __restrict__ A, const float* __restrict__ Wt,
    const float* __restrict__ bias, float* __restrict__ C,
    int M, int N, int K, int ldc)
{
    __shared__ float As[2][8][64];
    __shared__ float Bs[2][8][64];
    const int tid = threadIdx.x;
    const int tx = tid & 15, ty = tid >> 4;
    const int m0 = blockIdx.y * 64, n0 = blockIdx.x * 64;
    const int lr = tid >> 2, lc = (tid & 3) * 2;

    float acc[4][4] = {};

    auto load = [&](int tile, int buf) {
        int kt = tile * 8;
        float2 a2 = *reinterpret_cast<const float2*>(A + (size_t)(m0 + lr) * K + kt + lc);
        As[buf][lc][lr] = a2.x; As[buf][lc + 1][lr] = a2.y;
        float2 b2 = make_float2(0.0f, 0.0f);
        if (n0 + lr < N)
            b2 = *reinterpret_cast<const float2*>(Wt + (size_t)(n0 + lr) * K + kt + lc);
        Bs[buf][lc][lr] = b2.x; Bs[buf][lc + 1][lr] = b2.y;
    };

    const int ntiles = K >> 3;
    load(0, 0);
    __syncthreads();
    for (int tile = 0; tile < ntiles; ++tile) {
        int cur = tile & 1;
        if (tile + 1 < ntiles) load(tile + 1, cur ^ 1);
#pragma unroll
        for (int kk = 0; kk < 8; ++kk) {
            float4 av = *reinterpret_cast<const float4*>(&As[cur][kk][ty * 4]);
            float4 bv = *reinterpret_cast<const float4*>(&Bs[cur][kk][tx * 4]);
            float a[4] = {av.x, av.y, av.z, av.w};
            float bb[4] = {bv.x, bv.y, bv.z, bv.w};
#pragma unroll
            for (int mi = 0; mi < 4; ++mi)
#pragma unroll
                for (int ni = 0; ni < 4; ++ni)
                    acc[mi][ni] += a[mi] * bb[ni];
        }
        __syncthreads();
    }

#pragma unroll
    for (int mi = 0; mi < 4; ++mi) {
        int row = m0 + ty * 4 + mi;
#pragma unroll
        for (int ni = 0; ni < 4; ++ni) {
            int nn = n0 + tx * 4 + ni;
            if (nn < N) {
                float v = acc[mi][ni] + bias[nn];
                if (SIG) v = 1.0f / (1.0f + __expf(-v));
                C[(size_t)row * ldc + nn] = v;
            }
        }
    }
}

// ---------------------------------------------------------------------------
extern "C" void kernel_launch(void* const* d_in, const int* in_sizes, int n_in,
                              void* d_out, int out_size)
{
    const float* x   = (const float*)d_in[0];
    const float* lw  = (const float*)d_in[1];
    const float* lb  = (const float*)d_in[2];
    const float* wih = (const float*)d_in[3];
    const float* whh = (const float*)d_in[4];
    const float* bih = (const float*)d_in[5];
    const float* bhh = (const float*)d_in[6];
    const float* ow  = (const float*)d_in[7];
    const float* ob  = (const float*)d_in[8];
    float* out = (float*)d_out;

    float *cb, *xp, *gx0, *ys;
    uint32_t *hb32, *wib32, *whb32;
    int* flags;
    cudaGetSymbolAddress((void**)&cb,    g_c);
    cudaGetSymbolAddress((void**)&xp,    g_xp);
    cudaGetSymbolAddress((void**)&gx0,   g_gx0);
    cudaGetSymbolAddress((void**)&ys,    g_ys);
    cudaGetSymbolAddress((void**)&hb32,  g_hb32);
    cudaGetSymbolAddress((void**)&wib32, g_wib32);
    cudaGetSymbolAddress((void**)&whb32, g_whb32);
    cudaGetSymbolAddress((void**)&flags, g_flags);

    cudaFuncSetAttribute(cell_persist_kernel, cudaFuncAttributeMaxDynamicSharedMemorySize, SM_BYTES);

    int dev = 0, nsm = 132;
    cudaGetDevice(&dev);
    cudaDeviceGetAttribute(&nsm, cudaDevAttrMultiProcessorCount, dev);

    // ---- state init + weight conversion (graph nodes, deterministic) ----
    zero_kernel<<<2048, 256>>>((float*)hb32, LL * BB * HH);   // bf16 zeros (whole parity-buffered state)
    zero_kernel<<<2048, 256>>>(cb, LL * BB * HH);
    zero_kernel<<<40, 256>>>((float*)flags, LL * TT * 32);    // dependency flags
    f2bf_kernel<<<1024, 256>>>(wih, wib32, LL * G4 * HH / 2);
    f2bf_kernel<<<1024, 256>>>(whh, whb32, LL * G4 * HH / 2);

    // xp = x @ lw.T + lb
    gemm_bias_kernel<false><<<dim3(HH / 64, BB / 64), 256>>>(x, lw, lb, xp, BB, HH, LATENT, HH);
    // gx0 = xp @ wih[0].T + bih[0]  (constant over time, fp32)
    gemm_bias_kernel<false><<<dim3(G4 / 64, BB / 64), 256>>>(xp, wih, bih, gx0, BB, G4, HH, G4);

    // ---- persistent wavefront: ALL 320 cells in one launch ----
    cell_persist_kernel<<<nsm, 512, SM_BYTES>>>(bih, bhh);

    // out = sigmoid(ys @ ow.T + ob)
    gemm_bias_kernel<true><<<dim3((OUTN + 63) / 64, (BB * TT) / 64), 256>>>(
        ys, ow, ob, out, BB * TT, OUTN, HH, OUTN);
}

// round 14
// speedup vs baseline: 1.1320x; 1.1320x over previous
#include <cuda_runtime.h>
#include <cuda_bf16.h>
#include <math.h>
#include <stdint.h>

#define BB     4096
#define LATENT 128
#define HH     256
#define G4     1024   // 4*HH
#define OUTN   88
#define TT     64
#define LL     5

// ---------------- static device scratch (no allocations allowed) -------------
__device__ float    g_c[LL * BB * HH];
__device__ float    g_xp[BB * HH];
__device__ float    g_gx0[BB * G4];              // layer-0 input gates (const over t)
__device__ uint32_t g_ys32[BB * TT * HH / 2];    // [B][T][H] bf16 pairs
__device__ uint32_t g_hb32[LL * 2 * BB * HH / 2];   // h state, bf16 pairs, parity buffered
__device__ uint32_t g_wib32[LL * G4 * HH / 2];      // wih in bf16 pairs
__device__ uint32_t g_whb32[LL * G4 * HH / 2];      // whh in bf16 pairs
__device__ uint32_t g_owb32[OUTN * HH / 2];         // out_w in bf16 pairs

#define WIH_W (LL * G4 * HH / 2)
#define OW_W  (OUTN * HH / 2)

// ---------------------------------------------------------------------------
// Fused prelude kernels (few launches -> ncu -s 5 lands on a cell kernel)
__global__ void zero2_kernel(float* __restrict__ p1, int n1, float* __restrict__ p2, int n2) {
    int i = blockIdx.x * blockDim.x + threadIdx.x;
    int stride = gridDim.x * blockDim.x;
    for (; i < n1 + n2; i += stride) {
        if (i < n1) p1[i] = 0.0f; else p2[i - n1] = 0.0f;
    }
}

__device__ __forceinline__ uint32_t packbf(const float* src) {
    uint32_t lo = (uint32_t)__bfloat16_as_ushort(__float2bfloat16_rn(src[0]));
    uint32_t hi = (uint32_t)__bfloat16_as_ushort(__float2bfloat16_rn(src[1]));
    return lo | (hi << 16);
}
__global__ void cvt_all_kernel(const float* __restrict__ wih, const float* __restrict__ whh,
                               const float* __restrict__ ow,
                               uint32_t* __restrict__ wib, uint32_t* __restrict__ whb,
                               uint32_t* __restrict__ owb) {
    int i = blockIdx.x * blockDim.x + threadIdx.x;
    int stride = gridDim.x * blockDim.x;
    const int total = 2 * WIH_W + OW_W;
    for (; i < total; i += stride) {
        if (i < WIH_W)               wib[i] = packbf(wih + 2 * i);
        else if (i < 2 * WIH_W)      whb[i - WIH_W] = packbf(whh + 2 * (i - WIH_W));
        else                         owb[i - 2 * WIH_W] = packbf(ow + 2 * (i - 2 * WIH_W));
    }
}

__device__ __forceinline__ float sigf(float x) { return 1.0f / (1.0f + __expf(-x)); }
__device__ __forceinline__ float tanh_fast(float x) {
    float t = __expf(-2.0f * fabsf(x));
    float r = (1.0f - t) / (1.0f + t);
    return copysignf(r, x);
}
__device__ __forceinline__ void mma16(float* d, const uint32_t* a, uint32_t b0, uint32_t b1) {
    asm volatile(
        "mma.sync.aligned.m16n8k16.row.col.f32.bf16.bf16.f32 "
        "{%0,%1,%2,%3},{%4,%5,%6,%7},{%8,%9},{%0,%1,%2,%3};"
        : "+f"(d[0]), "+f"(d[1]), "+f"(d[2]), "+f"(d[3])
        : "r"(a[0]), "r"(a[1]), "r"(a[2]), "r"(a[3]), "r"(b0), "r"(b1));
}
__device__ __forceinline__ void ldm4(uint32_t* r, uint32_t addr) {
    asm volatile("ldmatrix.sync.aligned.m8n8.x4.shared.b16 {%0,%1,%2,%3}, [%4];"
                 : "=r"(r[0]), "=r"(r[1]), "=r"(r[2]), "=r"(r[3]) : "r"(addr));
}
__device__ __forceinline__ uint32_t smem_u32(const void* p) {
    uint32_t a;
    asm("{ .reg .u64 t; cvta.to.shared.u64 t, %1; cvt.u32.u64 %0, t; }" : "=r"(a) : "l"(p));
    return a;
}
__device__ __forceinline__ void cpasync16(uint32_t dst, const void* src) {
    asm volatile("cp.async.cg.shared.global [%0], [%1], 16;" :: "r"(dst), "l"(src) : "memory");
}
#define CP_COMMIT() asm volatile("cp.async.commit_group;" ::: "memory")
#define CP_WAIT1()  asm volatile("cp.async.wait_group 1;" ::: "memory")
#define CP_WAIT0()  asm volatile("cp.async.wait_group 0;" ::: "memory")

// ---------------------------------------------------------------------------
// Wavefront bf16 mma.sync LSTM cell (R12 structure — best known).
// ---------------------------------------------------------------------------
#define KT          64
#define RSW         36                 // row stride in words (32 data + 4 pad)
#define AROWS       128
#define BROWS       256
#define STAGE_WORDS ((AROWS + BROWS) * RSW)   // 13824 words = 55296 B
#define AOFFW       0
#define BOFFW       (AROWS * RSW)      // 4608
#define NSTAGE      3
#define GSTRIDE     258                // epilogue gate buffer row stride (floats)
#define SM_WORDS    (NSTAGE * STAGE_WORDS)    // 41472 words = 165888 B
#define SM_BYTES    (SM_WORDS * 4)

__global__ __launch_bounds__(512, 1) void cell_diag_kernel(
    int kdiag, int lmin,
    const float* __restrict__ bih_g, const float* __restrict__ bhh_g)
{
    extern __shared__ uint32_t sm[];
    const uint32_t sbase = smem_u32(sm);
    const int tid = threadIdx.x;
    const int wid = tid >> 5, lane = tid & 31;
    const int grp = lane >> 2, tig = lane & 3;
    const int wm = wid & 3, wn = wid >> 2;
    const int m0 = blockIdx.y * 128;
    const int n0 = blockIdx.x * 64;

    const int q = lane >> 3, rlane = lane & 7;
    const int ldm_row = rlane + (q & 1) * 8;
    const int ldm_colw = (q >> 1) * 4;

    const int l = lmin + blockIdx.z;
    const int t = kdiag - l;
    const size_t lsz = (size_t)BB * HH;
    const __nv_bfloat16* hb = reinterpret_cast<const __nv_bfloat16*>(g_hb32);
    __nv_bfloat16* hbw = reinterpret_cast<__nv_bfloat16*>(g_hb32);
    const __nv_bfloat16* wib = reinterpret_cast<const __nv_bfloat16*>(g_wib32);
    const __nv_bfloat16* whb = reinterpret_cast<const __nv_bfloat16*>(g_whb32);

    const __nv_bfloat16* h_prev = hb + (size_t)(l * 2 + ((t + 1) & 1)) * lsz;
    __nv_bfloat16*       h_o    = hbw + (size_t)(l * 2 + (t & 1)) * lsz;
    float*               cst    = g_c + (size_t)l * lsz;
    uint16_t*            ys     = (l == LL - 1)
        ? (reinterpret_cast<uint16_t*>(g_ys32) + (size_t)t * HH) : nullptr;

    const __nv_bfloat16 *A0, *W0, *A1, *W1;
    const float *bih, *gx0;
    int nst;
    const float* bhh = bhh_g + l * G4;
    if (l == 0) {
        A0 = h_prev; W0 = whb; A1 = nullptr; W1 = nullptr;
        nst = 4; bih = nullptr; gx0 = g_gx0;
    } else {
        A0 = hb + (size_t)((l - 1) * 2 + (t & 1)) * lsz;
        W0 = wib + (size_t)l * G4 * HH;
        A1 = h_prev;
        W1 = whb + (size_t)l * G4 * HH;
        nst = 8; bih = bih_g + l * G4; gx0 = nullptr;
    }
    const int half = 4;

    float acc[2][8][4] = {};

    auto load_stage = [&](int s, int buf) {
        const __nv_bfloat16* A = A0; const __nv_bfloat16* W = W0; int kt = s * KT;
        if (s >= half) { A = A1; W = W1; kt = (s - half) * KT; }
        const uint32_t base = sbase + (uint32_t)buf * (STAGE_WORDS * 4);
#pragma unroll
        for (int i = 0; i < 2; i++) {
            int c = i * 512 + tid;
            int r = c >> 3, sub = c & 7;
            cpasync16(base + (AOFFW + r * RSW + sub * 4) * 4,
                      A + (size_t)(m0 + r) * HH + kt + sub * 8);
        }
#pragma unroll
        for (int i = 0; i < 4; i++) {
            int c = i * 512 + tid;
            int r = c >> 3, sub = c & 7;
            int wrow = (r >> 6) * HH + n0 + (r & 63);
            cpasync16(base + (BOFFW + r * RSW + sub * 4) * 4,
                      W + (size_t)wrow * HH + kt + sub * 8);
        }
    };

    auto compute = [&](int buf) {
        const uint32_t sa = sbase + (uint32_t)buf * (STAGE_WORDS * 4) + AOFFW * 4;
        const uint32_t sb = sbase + (uint32_t)buf * (STAGE_WORDS * 4) + BOFFW * 4;
#pragma unroll
        for (int kk = 0; kk < 4; kk++) {
            const int k0 = kk * 8;
            uint32_t af[2][4];
#pragma unroll
            for (int mt = 0; mt < 2; mt++) {
                int ra = wm * 32 + mt * 16;
                ldm4(af[mt], sa + ((ra + ldm_row) * RSW + k0 + ldm_colw) * 4);
            }
            uint32_t bf[8][2];
#pragma unroll
            for (int ntp = 0; ntp < 4; ntp++) {
                int rb = wn * 64 + ntp * 16;
                uint32_t r4[4];
                ldm4(r4, sb + ((rb + ldm_row) * RSW + k0 + ldm_colw) * 4);
                bf[2 * ntp][0] = r4[0]; bf[2 * ntp + 1][0] = r4[1];
                bf[2 * ntp][1] = r4[2]; bf[2 * ntp + 1][1] = r4[3];
            }
#pragma unroll
            for (int nt = 0; nt < 8; nt++)
#pragma unroll
                for (int mt = 0; mt < 2; mt++)
                    mma16(acc[mt][nt], af[mt], bf[nt][0], bf[nt][1]);
        }
    };

    load_stage(0, 0); CP_COMMIT();
    load_stage(1, 1); CP_COMMIT();
    for (int s = 0; s < nst; s++) {
        CP_WAIT1();
        __syncthreads();
        if (s + 2 < nst) load_stage(s + 2, (s + 2) % NSTAGE);
        CP_COMMIT();
        compute(s % NSTAGE);
    }
    __syncthreads();

    float* smf = reinterpret_cast<float*>(sm);
#pragma unroll
    for (int mt = 0; mt < 2; mt++) {
#pragma unroll
        for (int nt = 0; nt < 8; nt++) {
            int row = wm * 32 + mt * 16 + grp;
            int col = wn * 64 + nt * 8 + 2 * tig;
            *reinterpret_cast<float2*>(&smf[row * GSTRIDE + col]) =
                make_float2(acc[mt][nt][0], acc[mt][nt][1]);
            *reinterpret_cast<float2*>(&smf[(row + 8) * GSTRIDE + col]) =
                make_float2(acc[mt][nt][2], acc[mt][nt][3]);
        }
    }
    __syncthreads();

    const int u = tid & 63;
    const int n = n0 + u;
    const int bloc0 = (tid >> 6) * 16;

    float bsum[4];
#pragma unroll
    for (int gg = 0; gg < 4; gg++) {
        float v = bhh[gg * HH + n];
        if (bih) v += bih[gg * HH + n];
        bsum[gg] = v;
    }

    uint16_t* h_o16 = reinterpret_cast<uint16_t*>(h_o);
    for (int i = 0; i < 16; i++) {
        const int bl = bloc0 + i;
        const int gb = m0 + bl;
        float pre[4];
#pragma unroll
        for (int gg = 0; gg < 4; gg++)
            pre[gg] = smf[bl * GSTRIDE + gg * 64 + u] + bsum[gg];
        if (gx0) {
#pragma unroll
            for (int gg = 0; gg < 4; gg++)
                pre[gg] += gx0[(size_t)gb * G4 + gg * HH + n];
        }
        float co = cst[(size_t)gb * HH + n];
        float iv = sigf(pre[0]);
        float fv = sigf(pre[1]);
        float gv = tanh_fast(pre[2]);
        float ov = sigf(pre[3]);
        float cn = fv * co + iv * gv;
        float hn = ov * tanh_fast(cn);
        cst[(size_t)gb * HH + n] = cn;
        uint16_t hb16 = __bfloat16_as_ushort(__float2bfloat16_rn(hn));
        h_o16[(size_t)gb * HH + n] = hb16;
        if (ys) ys[(size_t)gb * (TT * HH) + n] = hb16;
    }
}

// ---------------------------------------------------------------------------
// bf16 mma output GEMM: out = sigmoid(ys @ ow.T + ob), M=BB*TT, N=88, K=256.
// CTA: 128 rows x 96 cols (rows 88..95 of W zero-padded). 256 threads,
// 8 warps (4m x 2n), warp tile 32x48. K split in 2 stages of 128.
// ---------------------------------------------------------------------------
#define OKT    128
#define ORSW   68                      // 64 data words + 4 pad
#define OAR    128
#define OBR    96
#define OSTW   ((OAR + OBR) * ORSW)    // 15232 words = 60928 B
#define OSM_BYTES (2 * OSTW * 4)       // 121856 B

__global__ __launch_bounds__(256, 1) void out_gemm_kernel(
    const float* __restrict__ bias, float* __restrict__ out)
{
    extern __shared__ uint32_t sm[];
    const uint32_t sbase = smem_u32(sm);
    const int tid = threadIdx.x;
    const int wid = tid >> 5, lane = tid & 31;
    const int grp = lane >> 2, tig = lane & 3;
    const int wm = wid & 3, wn = wid >> 2;
    const int m0 = blockIdx.x * 128;

    const int q = lane >> 3, rlane = lane & 7;
    const int ldm_row = rlane + (q & 1) * 8;
    const int ldm_colw = (q >> 1) * 4;

    const __nv_bfloat16* A = reinterpret_cast<const __nv_bfloat16*>(g_ys32);
    const __nv_bfloat16* W = reinterpret_cast<const __nv_bfloat16*>(g_owb32);

    float acc[2][6][4] = {};

    auto load_stage = [&](int s, int buf) {
        const int kt = s * OKT;
        const uint32_t base = sbase + (uint32_t)buf * (OSTW * 4);
        // A: 128 rows x 128 k = 2048 chunks, 8 per thread
#pragma unroll
        for (int i = 0; i < 8; i++) {
            int c = i * 256 + tid;
            int r = c >> 4, sub = c & 15;
            cpasync16(base + (r * ORSW + sub * 4) * 4,
                      A + (size_t)(m0 + r) * HH + kt + sub * 8);
        }
        // B: 96 rows x 128 k = 1536 chunks, 6 per thread; rows >= 88 zeroed
#pragma unroll
        for (int i = 0; i < 6; i++) {
            int c = i * 256 + tid;
            int r = c >> 4, sub = c & 15;
            uint32_t dst = base + ((OAR + r) * ORSW + sub * 4) * 4;
            if (r < OUTN) {
                cpasync16(dst, W + (size_t)r * HH + kt + sub * 8);
            } else {
                *reinterpret_cast<uint4*>(
                    reinterpret_cast<char*>(sm) + (dst - sbase)) = make_uint4(0, 0, 0, 0);
            }
        }
    };

    auto compute = [&](int buf) {
        const uint32_t sa = sbase + (uint32_t)buf * (OSTW * 4);
        const uint32_t sb = sa + OAR * ORSW * 4;
#pragma unroll
        for (int kk = 0; kk < 8; kk++) {
            const int k0 = kk * 8;
            uint32_t af[2][4];
#pragma unroll
            for (int mt = 0; mt < 2; mt++) {
                int ra = wm * 32 + mt * 16;
                ldm4(af[mt], sa + ((ra + ldm_row) * ORSW + k0 + ldm_colw) * 4);
            }
            uint32_t bf[6][2];
#pragma unroll
            for (int ntp = 0; ntp < 3; ntp++) {
                int rb = wn * 48 + ntp * 16;
                uint32_t r4[4];
                ldm4(r4, sb + ((rb + ldm_row) * ORSW + k0 + ldm_colw) * 4);
                bf[2 * ntp][0] = r4[0]; bf[2 * ntp + 1][0] = r4[1];
                bf[2 * ntp][1] = r4[2]; bf[2 * ntp + 1][1] = r4[3];
            }
#pragma unroll
            for (int nt = 0; nt < 6; nt++)
#pragma unroll
                for (int mt = 0; mt < 2; mt++)
                    mma16(acc[mt][nt], af[mt], bf[nt][0], bf[nt][1]);
        }
    };

    load_stage(0, 0); CP_COMMIT();
    load_stage(1, 1); CP_COMMIT();
    CP_WAIT1(); __syncthreads(); compute(0);
    CP_WAIT0(); __syncthreads(); compute(1);

    // epilogue: bias + sigmoid, guarded stores (cols < 88)
#pragma unroll
    for (int mt = 0; mt < 2; mt++) {
#pragma unroll
        for (int nt = 0; nt < 6; nt++) {
            int col = wn * 48 + nt * 8 + 2 * tig;
            int row = m0 + wm * 32 + mt * 16 + grp;
            if (col < OUTN) {
                float b0 = bias[col];
                out[(size_t)row * OUTN + col]       = sigf(acc[mt][nt][0] + b0);
                out[(size_t)(row + 8) * OUTN + col] = sigf(acc[mt][nt][2] + b0);
            }
            if (col + 1 < OUTN) {
                float b1 = bias[col + 1];
                out[(size_t)row * OUTN + col + 1]       = sigf(acc[mt][nt][1] + b1);
                out[(size_t)(row + 8) * OUTN + col + 1] = sigf(acc[mt][nt][3] + b1);
            }
        }
    }
}

// ---------------------------------------------------------------------------
// SIMT GEMM (projections only)
template <bool SIG>
__global__ __launch_bounds__(256) void gemm_bias_kernel(
    const float* __restrict__ A, const float* __restrict__ Wt,
    const float* __restrict__ bias, float* __restrict__ C,
    int M, int N, int K, int ldc)
{
    __shared__ float As[2][8][64];
    __shared__ float Bs[2][8][64];
    const int tid = threadIdx.x;
    const int tx = tid & 15, ty = tid >> 4;
    const int m0 = blockIdx.y * 64, n0 = blockIdx.x * 64;
    const int lr = tid >> 2, lc = (tid & 3) * 2;

    float acc[4][4] = {};

    auto load = [&](int tile, int buf) {
        int kt = tile * 8;
        float2 a2 = *reinterpret_cast<const float2*>(A + (size_t)(m0 + lr) * K + kt + lc);
        As[buf][lc][lr] = a2.x; As[buf][lc + 1][lr] = a2.y;
        float2 b2 = make_float2(0.0f, 0.0f);
        if (n0 + lr < N)
            b2 = *reinterpret_cast<const float2*>(Wt + (size_t)(n0 + lr) * K + kt + lc);
        Bs[buf][lc][lr] = b2.x; Bs[buf][lc + 1][lr] = b2.y;
    };

    const int ntiles = K >> 3;
    load(0, 0);
    __syncthreads();
    for (int tile = 0; tile < ntiles; ++tile) {
        int cur = tile & 1;
        if (tile + 1 < ntiles) load(tile + 1, cur ^ 1);
#pragma unroll
        for (int kk = 0; kk < 8; ++kk) {
            float4 av = *reinterpret_cast<const float4*>(&As[cur][kk][ty * 4]);
            float4 bv = *reinterpret_cast<const float4*>(&Bs[cur][kk][tx * 4]);
            float a[4] = {av.x, av.y, av.z, av.w};
            float bb[4] = {bv.x, bv.y, bv.z, bv.w};
#pragma unroll
            for (int mi = 0; mi < 4; ++mi)
#pragma unroll
                for (int ni = 0; ni < 4; ++ni)
                    acc[mi][ni] += a[mi] * bb[ni];
        }
        __syncthreads();
    }

#pragma unroll
    for (int mi = 0; mi < 4; ++mi) {
        int row = m0 + ty * 4 + mi;
#pragma unroll
        for (int ni = 0; ni < 4; ++ni) {
            int nn = n0 + tx * 4 + ni;
            if (nn < N) {
                float v = acc[mi][ni] + bias[nn];
                if (SIG) v = 1.0f / (1.0f + __expf(-v));
                C[(size_t)row * ldc + nn] = v;
            }
        }
    }
}

// ---------------------------------------------------------------------------
extern "C" void kernel_launch(void* const* d_in, const int* in_sizes, int n_in,
                              void* d_out, int out_size)
{
    const float* x   = (const float*)d_in[0];
    const float* lw  = (const float*)d_in[1];
    const float* lb  = (const float*)d_in[2];
    const float* wih = (const float*)d_in[3];
    const float* whh = (const float*)d_in[4];
    const float* bih = (const float*)d_in[5];
    const float* bhh = (const float*)d_in[6];
    const float* ow  = (const float*)d_in[7];
    const float* ob  = (const float*)d_in[8];
    float* out = (float*)d_out;

    float *cb, *xp, *gx0;
    uint32_t *hb32, *wib32, *whb32, *owb32;
    cudaGetSymbolAddress((void**)&cb,    g_c);
    cudaGetSymbolAddress((void**)&xp,    g_xp);
    cudaGetSymbolAddress((void**)&gx0,   g_gx0);
    cudaGetSymbolAddress((void**)&hb32,  g_hb32);
    cudaGetSymbolAddress((void**)&wib32, g_wib32);
    cudaGetSymbolAddress((void**)&whb32, g_whb32);
    cudaGetSymbolAddress((void**)&owb32, g_owb32);

    cudaFuncSetAttribute(cell_diag_kernel, cudaFuncAttributeMaxDynamicSharedMemorySize, SM_BYTES);
    cudaFuncSetAttribute(out_gemm_kernel, cudaFuncAttributeMaxDynamicSharedMemorySize, OSM_BYTES);

    // ---- prelude: 4 launches (so ncu -s 5 profiles a cell kernel) ----
    zero2_kernel<<<2048, 256>>>((float*)hb32, LL * BB * HH, cb, LL * BB * HH);
    cvt_all_kernel<<<1024, 256>>>(wih, whh, ow, wib32, whb32, owb32);
    gemm_bias_kernel<false><<<dim3(HH / 64, BB / 64), 256>>>(x, lw, lb, xp, BB, HH, LATENT, HH);
    gemm_bias_kernel<false><<<dim3(G4 / 64, BB / 64), 256>>>(xp, wih, bih, gx0, BB, G4, HH, G4);

    // ---- wavefront over diagonals k = l + t ----
    for (int k = 0; k < TT + LL - 1; ++k) {
        int lmin = k - (TT - 1); if (lmin < 0) lmin = 0;
        int lmax = k;            if (lmax > LL - 1) lmax = LL - 1;
        dim3 grid(4, 32, (unsigned)(lmax - lmin + 1));
        cell_diag_kernel<<<grid, 512, SM_BYTES>>>(k, lmin, bih, bhh);
    }

    // ---- bf16 mma output GEMM ----
    out_gemm_kernel<<<(BB * TT) / 128, 256, OSM_BYTES>>>(ob, out);
}

// round 15
// speedup vs baseline: 1.2281x; 1.0848x over previous
#include <cuda_runtime.h>
#include <cuda_bf16.h>
#include <math.h>
#include <stdint.h>

#define BB     4096
#define LATENT 128
#define HH     256
#define G4     1024   // 4*HH
#define OUTN   88
#define TT     64
#define LL     5

// ---------------- static device scratch (no allocations allowed) -------------
__device__ float    g_c[LL * BB * HH];
__device__ float    g_xp[BB * HH];
__device__ float    g_gx0[BB * G4];              // layer-0 input gates (const over t)
__device__ uint32_t g_ys32[BB * TT * HH / 2];    // [B][T][H] bf16 pairs
__device__ uint32_t g_hb32[LL * 2 * BB * HH / 2];   // h state, bf16 pairs, parity buffered
__device__ uint32_t g_wib32[LL * G4 * HH / 2];      // wih in bf16 pairs
__device__ uint32_t g_whb32[LL * G4 * HH / 2];      // whh in bf16 pairs
__device__ uint32_t g_owb32[OUTN * HH / 2];         // out_w in bf16 pairs

#define WIH_W (LL * G4 * HH / 2)
#define OW_W  (OUTN * HH / 2)

// ---------------------------------------------------------------------------
__global__ void zero2_kernel(float* __restrict__ p1, int n1, float* __restrict__ p2, int n2) {
    int i = blockIdx.x * blockDim.x + threadIdx.x;
    int stride = gridDim.x * blockDim.x;
    for (; i < n1 + n2; i += stride) {
        if (i < n1) p1[i] = 0.0f; else p2[i - n1] = 0.0f;
    }
}

__device__ __forceinline__ uint32_t packbf(const float* src) {
    uint32_t lo = (uint32_t)__bfloat16_as_ushort(__float2bfloat16_rn(src[0]));
    uint32_t hi = (uint32_t)__bfloat16_as_ushort(__float2bfloat16_rn(src[1]));
    return lo | (hi << 16);
}
__global__ void cvt_all_kernel(const float* __restrict__ wih, const float* __restrict__ whh,
                               const float* __restrict__ ow,
                               uint32_t* __restrict__ wib, uint32_t* __restrict__ whb,
                               uint32_t* __restrict__ owb) {
    int i = blockIdx.x * blockDim.x + threadIdx.x;
    int stride = gridDim.x * blockDim.x;
    const int total = 2 * WIH_W + OW_W;
    for (; i < total; i += stride) {
        if (i < WIH_W)               wib[i] = packbf(wih + 2 * i);
        else if (i < 2 * WIH_W)      whb[i - WIH_W] = packbf(whh + 2 * (i - WIH_W));
        else                         owb[i - 2 * WIH_W] = packbf(ow + 2 * (i - 2 * WIH_W));
    }
}

__device__ __forceinline__ float sigf(float x) { return 1.0f / (1.0f + __expf(-x)); }
__device__ __forceinline__ float tanh_fast(float x) {
    float t = __expf(-2.0f * fabsf(x));
    float r = (1.0f - t) / (1.0f + t);
    return copysignf(r, x);
}
__device__ __forceinline__ void mma16(float* d, const uint32_t* a, uint32_t b0, uint32_t b1) {
    asm volatile(
        "mma.sync.aligned.m16n8k16.row.col.f32.bf16.bf16.f32 "
        "{%0,%1,%2,%3},{%4,%5,%6,%7},{%8,%9},{%0,%1,%2,%3};"
        : "+f"(d[0]), "+f"(d[1]), "+f"(d[2]), "+f"(d[3])
        : "r"(a[0]), "r"(a[1]), "r"(a[2]), "r"(a[3]), "r"(b0), "r"(b1));
}
__device__ __forceinline__ void ldm4(uint32_t* r, uint32_t addr) {
    asm volatile("ldmatrix.sync.aligned.m8n8.x4.shared.b16 {%0,%1,%2,%3}, [%4];"
                 : "=r"(r[0]), "=r"(r[1]), "=r"(r[2]), "=r"(r[3]) : "r"(addr));
}
__device__ __forceinline__ uint32_t smem_u32(const void* p) {
    uint32_t a;
    asm("{ .reg .u64 t; cvta.to.shared.u64 t, %1; cvt.u32.u64 %0, t; }" : "=r"(a) : "l"(p));
    return a;
}
__device__ __forceinline__ void cpasync16(uint32_t dst, const void* src) {
    asm volatile("cp.async.cg.shared.global [%0], [%1], 16;" :: "r"(dst), "l"(src) : "memory");
}
#define CP_COMMIT() asm volatile("cp.async.commit_group;" ::: "memory")
#define CP_WAIT1()  asm volatile("cp.async.wait_group 1;" ::: "memory")
#define CP_WAIT0()  asm volatile("cp.async.wait_group 0;" ::: "memory")

// ---------------------------------------------------------------------------
// Wavefront bf16 mma.sync LSTM cell — 2 CTAs/SM variant.
// CTA: 256 threads, tile 64 batch x 256 gate-cols (4 gates x 64 units).
// 8 warps (2m x 4n), warp tile 32x64 via m16n8k16 + ldmatrix.x4.
// KT=64, double-buffered cp.async, ONE barrier per stage; latency coverage
// comes primarily from the co-resident sibling CTA.
// ---------------------------------------------------------------------------
#define KT          64
#define RSW         36                 // row stride in words (32 data + 4 pad)
#define AROWS       64
#define BROWS       256
#define STAGE_WORDS ((AROWS + BROWS) * RSW)   // 11520 words = 46080 B
#define AOFFW       0
#define BOFFW       (AROWS * RSW)      // 2304
#define NSTAGE      2
#define GSTRIDE     258                // epilogue gate buffer row stride (floats)
#define SM_WORDS    (NSTAGE * STAGE_WORDS)    // 23040 words = 92160 B (> 64*258=16512)
#define SM_BYTES    (SM_WORDS * 4)

__global__ __launch_bounds__(256, 2) void cell_diag_kernel(
    int kdiag, int lmin,
    const float* __restrict__ bih_g, const float* __restrict__ bhh_g)
{
    extern __shared__ uint32_t sm[];
    const uint32_t sbase = smem_u32(sm);
    const int tid = threadIdx.x;
    const int wid = tid >> 5, lane = tid & 31;
    const int grp = lane >> 2, tig = lane & 3;
    const int wm = wid & 1, wn = wid >> 1;
    const int m0 = blockIdx.y * 64;
    const int n0 = blockIdx.x * 64;

    const int q = lane >> 3, rlane = lane & 7;
    const int ldm_row = rlane + (q & 1) * 8;
    const int ldm_colw = (q >> 1) * 4;

    const int l = lmin + blockIdx.z;
    const int t = kdiag - l;
    const size_t lsz = (size_t)BB * HH;
    const __nv_bfloat16* hb = reinterpret_cast<const __nv_bfloat16*>(g_hb32);
    __nv_bfloat16* hbw = reinterpret_cast<__nv_bfloat16*>(g_hb32);
    const __nv_bfloat16* wib = reinterpret_cast<const __nv_bfloat16*>(g_wib32);
    const __nv_bfloat16* whb = reinterpret_cast<const __nv_bfloat16*>(g_whb32);

    const __nv_bfloat16* h_prev = hb + (size_t)(l * 2 + ((t + 1) & 1)) * lsz;
    __nv_bfloat16*       h_o    = hbw + (size_t)(l * 2 + (t & 1)) * lsz;
    float*               cst    = g_c + (size_t)l * lsz;
    uint16_t*            ys     = (l == LL - 1)
        ? (reinterpret_cast<uint16_t*>(g_ys32) + (size_t)t * HH) : nullptr;

    const __nv_bfloat16 *A0, *W0, *A1, *W1;
    const float *bih, *gx0;
    int nst;
    const float* bhh = bhh_g + l * G4;
    if (l == 0) {
        A0 = h_prev; W0 = whb; A1 = nullptr; W1 = nullptr;
        nst = 4; bih = nullptr; gx0 = g_gx0;
    } else {
        A0 = hb + (size_t)((l - 1) * 2 + (t & 1)) * lsz;
        W0 = wib + (size_t)l * G4 * HH;
        A1 = h_prev;
        W1 = whb + (size_t)l * G4 * HH;
        nst = 8; bih = bih_g + l * G4; gx0 = nullptr;
    }
    const int half = 4;

    float acc[2][8][4] = {};

    auto load_stage = [&](int s, int buf) {
        const __nv_bfloat16* A = A0; const __nv_bfloat16* W = W0; int kt = s * KT;
        if (s >= half) { A = A1; W = W1; kt = (s - half) * KT; }
        const uint32_t base = sbase + (uint32_t)buf * (STAGE_WORDS * 4);
        // A: 64 rows x 64 bf16 = 512 16B-chunks, 2 per thread
#pragma unroll
        for (int i = 0; i < 2; i++) {
            int c = i * 256 + tid;
            int r = c >> 3, sub = c & 7;
            cpasync16(base + (AOFFW + r * RSW + sub * 4) * 4,
                      A + (size_t)(m0 + r) * HH + kt + sub * 8);
        }
        // B: 256 rows x 64 bf16 = 2048 chunks, 8 per thread
#pragma unroll
        for (int i = 0; i < 8; i++) {
            int c = i * 256 + tid;
            int r = c >> 3, sub = c & 7;
            int wrow = (r >> 6) * HH + n0 + (r & 63);
            cpasync16(base + (BOFFW + r * RSW + sub * 4) * 4,
                      W + (size_t)wrow * HH + kt + sub * 8);
        }
    };

    auto compute = [&](int buf) {
        const uint32_t sa = sbase + (uint32_t)buf * (STAGE_WORDS * 4) + AOFFW * 4;
        const uint32_t sb = sbase + (uint32_t)buf * (STAGE_WORDS * 4) + BOFFW * 4;
#pragma unroll
        for (int kk = 0; kk < 4; kk++) {
            const int k0 = kk * 8;
            uint32_t af[2][4];
#pragma unroll
            for (int mt = 0; mt < 2; mt++) {
                int ra = wm * 32 + mt * 16;
                ldm4(af[mt], sa + ((ra + ldm_row) * RSW + k0 + ldm_colw) * 4);
            }
            uint32_t bf[8][2];
#pragma unroll
            for (int ntp = 0; ntp < 4; ntp++) {
                int rb = wn * 64 + ntp * 16;
                uint32_t r4[4];
                ldm4(r4, sb + ((rb + ldm_row) * RSW + k0 + ldm_colw) * 4);
                bf[2 * ntp][0] = r4[0]; bf[2 * ntp + 1][0] = r4[1];
                bf[2 * ntp][1] = r4[2]; bf[2 * ntp + 1][1] = r4[3];
            }
#pragma unroll
            for (int nt = 0; nt < 8; nt++)
#pragma unroll
                for (int mt = 0; mt < 2; mt++)
                    mma16(acc[mt][nt], af[mt], bf[nt][0], bf[nt][1]);
        }
    };

    // ---- double-buffer pipeline, one barrier per stage ----
    load_stage(0, 0); CP_COMMIT();
    for (int s = 0; s < nst; s++) {
        CP_WAIT0();                 // stage s landed
        __syncthreads();            // visible to all; all warps done with compute(s-1)
        if (s + 1 < nst) { load_stage(s + 1, (s + 1) & 1); CP_COMMIT(); }
        compute(s & 1);
    }
    __syncthreads();                // staging -> gate-buffer reuse

    // ---- gate pre-activations to smem ----
    float* smf = reinterpret_cast<float*>(sm);
#pragma unroll
    for (int mt = 0; mt < 2; mt++) {
#pragma unroll
        for (int nt = 0; nt < 8; nt++) {
            int row = wm * 32 + mt * 16 + grp;
            int col = wn * 64 + nt * 8 + 2 * tig;
            *reinterpret_cast<float2*>(&smf[row * GSTRIDE + col]) =
                make_float2(acc[mt][nt][0], acc[mt][nt][1]);
            *reinterpret_cast<float2*>(&smf[(row + 8) * GSTRIDE + col]) =
                make_float2(acc[mt][nt][2], acc[mt][nt][3]);
        }
    }
    __syncthreads();

    // ---- epilogue: LSTM cell, coalesced global I/O ----
    const int u = tid & 63;
    const int n = n0 + u;
    const int bloc0 = (tid >> 6) * 16;   // 4 groups x 16 rows = 64

    float bsum[4];
#pragma unroll
    for (int gg = 0; gg < 4; gg++) {
        float v = bhh[gg * HH + n];
        if (bih) v += bih[gg * HH + n];
        bsum[gg] = v;
    }

    uint16_t* h_o16 = reinterpret_cast<uint16_t*>(h_o);
    for (int i = 0; i < 16; i++) {
        const int bl = bloc0 + i;
        const int gb = m0 + bl;
        float pre[4];
#pragma unroll
        for (int gg = 0; gg < 4; gg++)
            pre[gg] = smf[bl * GSTRIDE + gg * 64 + u] + bsum[gg];
        if (gx0) {
#pragma unroll
            for (int gg = 0; gg < 4; gg++)
                pre[gg] += gx0[(size_t)gb * G4 + gg * HH + n];
        }
        float co = cst[(size_t)gb * HH + n];
        float iv = sigf(pre[0]);
        float fv = sigf(pre[1]);
        float gv = tanh_fast(pre[2]);
        float ov = sigf(pre[3]);
        float cn = fv * co + iv * gv;
        float hn = ov * tanh_fast(cn);
        cst[(size_t)gb * HH + n] = cn;
        uint16_t hb16 = __bfloat16_as_ushort(__float2bfloat16_rn(hn));
        h_o16[(size_t)gb * HH + n] = hb16;
        if (ys) ys[(size_t)gb * (TT * HH) + n] = hb16;
    }
}

// ---------------------------------------------------------------------------
// bf16 mma output GEMM: out = sigmoid(ys @ ow.T + ob), M=BB*TT, N=88, K=256.
// ---------------------------------------------------------------------------
#define OKT    128
#define ORSW   68
#define OAR    128
#define OBR    96
#define OSTW   ((OAR + OBR) * ORSW)
#define OSM_BYTES (2 * OSTW * 4)

__global__ __launch_bounds__(256, 1) void out_gemm_kernel(
    const float* __restrict__ bias, float* __restrict__ out)
{
    extern __shared__ uint32_t sm[];
    const uint32_t sbase = smem_u32(sm);
    const int tid = threadIdx.x;
    const int wid = tid >> 5, lane = tid & 31;
    const int grp = lane >> 2, tig = lane & 3;
    const int wm = wid & 3, wn = wid >> 2;
    const int m0 = blockIdx.x * 128;

    const int q = lane >> 3, rlane = lane & 7;
    const int ldm_row = rlane + (q & 1) * 8;
    const int ldm_colw = (q >> 1) * 4;

    const __nv_bfloat16* A = reinterpret_cast<const __nv_bfloat16*>(g_ys32);
    const __nv_bfloat16* W = reinterpret_cast<const __nv_bfloat16*>(g_owb32);

    float acc[2][6][4] = {};

    auto load_stage = [&](int s, int buf) {
        const int kt = s * OKT;
        const uint32_t base = sbase + (uint32_t)buf * (OSTW * 4);
#pragma unroll
        for (int i = 0; i < 8; i++) {
            int c = i * 256 + tid;
            int r = c >> 4, sub = c & 15;
            cpasync16(base + (r * ORSW + sub * 4) * 4,
                      A + (size_t)(m0 + r) * HH + kt + sub * 8);
        }
#pragma unroll
        for (int i = 0; i < 6; i++) {
            int c = i * 256 + tid;
            int r = c >> 4, sub = c & 15;
            uint32_t dst = base + ((OAR + r) * ORSW + sub * 4) * 4;
            if (r < OUTN) {
                cpasync16(dst, W + (size_t)r * HH + kt + sub * 8);
            } else {
                *reinterpret_cast<uint4*>(
                    reinterpret_cast<char*>(sm) + (dst - sbase)) = make_uint4(0, 0, 0, 0);
            }
        }
    };

    auto compute = [&](int buf) {
        const uint32_t sa = sbase + (uint32_t)buf * (OSTW * 4);
        const uint32_t sb = sa + OAR * ORSW * 4;
#pragma unroll
        for (int kk = 0; kk < 8; kk++) {
            const int k0 = kk * 8;
            uint32_t af[2][4];
#pragma unroll
            for (int mt = 0; mt < 2; mt++) {
                int ra = wm * 32 + mt * 16;
                ldm4(af[mt], sa + ((ra + ldm_row) * ORSW + k0 + ldm_colw) * 4);
            }
            uint32_t bf[6][2];
#pragma unroll
            for (int ntp = 0; ntp < 3; ntp++) {
                int rb = wn * 48 + ntp * 16;
                uint32_t r4[4];
                ldm4(r4, sb + ((rb + ldm_row) * ORSW + k0 + ldm_colw) * 4);
                bf[2 * ntp][0] = r4[0]; bf[2 * ntp + 1][0] = r4[1];
                bf[2 * ntp][1] = r4[2]; bf[2 * ntp + 1][1] = r4[3];
            }
#pragma unroll
            for (int nt = 0; nt < 6; nt++)
#pragma unroll
                for (int mt = 0; mt < 2; mt++)
                    mma16(acc[mt][nt], af[mt], bf[nt][0], bf[nt][1]);
        }
    };

    load_stage(0, 0); CP_COMMIT();
    load_stage(1, 1); CP_COMMIT();
    CP_WAIT1(); __syncthreads(); compute(0);
    CP_WAIT0(); __syncthreads(); compute(1);

#pragma unroll
    for (int mt = 0; mt < 2; mt++) {
#pragma unroll
        for (int nt = 0; nt < 6; nt++) {
            int col = wn * 48 + nt * 8 + 2 * tig;
            int row = m0 + wm * 32 + mt * 16 + grp;
            if (col < OUTN) {
                float b0 = bias[col];
                out[(size_t)row * OUTN + col]       = sigf(acc[mt][nt][0] + b0);
                out[(size_t)(row + 8) * OUTN + col] = sigf(acc[mt][nt][2] + b0);
            }
            if (col + 1 < OUTN) {
                float b1 = bias[col + 1];
                out[(size_t)row * OUTN + col + 1]       = sigf(acc[mt][nt][1] + b1);
                out[(size_t)(row + 8) * OUTN + col + 1] = sigf(acc[mt][nt][3] + b1);
            }
        }
    }
}

// ---------------------------------------------------------------------------
// SIMT GEMM (projections only)
template <bool SIG>
__global__ __launch_bounds__(256) void gemm_bias_kernel(
    const float* __restrict__ A, const float* __restrict__ Wt,
    const float* __restrict__ bias, float* __restrict__ C,
    int M, int N, int K, int ldc)
{
    __shared__ float As[2][8][64];
    __shared__ float Bs[2][8][64];
    const int tid = threadIdx.x;
    const int tx = tid & 15, ty = tid >> 4;
    const int m0 = blockIdx.y * 64, n0 = blockIdx.x * 64;
    const int lr = tid >> 2, lc = (tid & 3) * 2;

    float acc[4][4] = {};

    auto load = [&](int tile, int buf) {
        int kt = tile * 8;
        float2 a2 = *reinterpret_cast<const float2*>(A + (size_t)(m0 + lr) * K + kt + lc);
        As[buf][lc][lr] = a2.x; As[buf][lc + 1][lr] = a2.y;
        float2 b2 = make_float2(0.0f, 0.0f);
        if (n0 + lr < N)
            b2 = *reinterpret_cast<const float2*>(Wt + (size_t)(n0 + lr) * K + kt + lc);
        Bs[buf][lc][lr] = b2.x; Bs[buf][lc + 1][lr] = b2.y;
    };

    const int ntiles = K >> 3;
    load(0, 0);
    __syncthreads();
    for (int tile = 0; tile < ntiles; ++tile) {
        int cur = tile & 1;
        if (tile + 1 < ntiles) load(tile + 1, cur ^ 1);
#pragma unroll
        for (int kk = 0; kk < 8; ++kk) {
            float4 av = *reinterpret_cast<const float4*>(&As[cur][kk][ty * 4]);
            float4 bv = *reinterpret_cast<const float4*>(&Bs[cur][kk][tx * 4]);
            float a[4] = {av.x, av.y, av.z, av.w};
            float bb[4] = {bv.x, bv.y, bv.z, bv.w};
#pragma unroll
            for (int mi = 0; mi < 4; ++mi)
#pragma unroll
                for (int ni = 0; ni < 4; ++ni)
                    acc[mi][ni] += a[mi] * bb[ni];
        }
        __syncthreads();
    }

#pragma unroll
    for (int mi = 0; mi < 4; ++mi) {
        int row = m0 + ty * 4 + mi;
#pragma unroll
        for (int ni = 0; ni < 4; ++ni) {
            int nn = n0 + tx * 4 + ni;
            if (nn < N) {
                float v = acc[mi][ni] + bias[nn];
                if (SIG) v = 1.0f / (1.0f + __expf(-v));
                C[(size_t)row * ldc + nn] = v;
            }
        }
    }
}

// ---------------------------------------------------------------------------
extern "C" void kernel_launch(void* const* d_in, const int* in_sizes, int n_in,
                              void* d_out, int out_size)
{
    const float* x   = (const float*)d_in[0];
    const float* lw  = (const float*)d_in[1];
    const float* lb  = (const float*)d_in[2];
    const float* wih = (const float*)d_in[3];
    const float* whh = (const float*)d_in[4];
    const float* bih = (const float*)d_in[5];
    const float* bhh = (const float*)d_in[6];
    const float* ow  = (const float*)d_in[7];
    const float* ob  = (const float*)d_in[8];
    float* out = (float*)d_out;

    float *cb, *xp, *gx0;
    uint32_t *hb32, *wib32, *whb32, *owb32;
    cudaGetSymbolAddress((void**)&cb,    g_c);
    cudaGetSymbolAddress((void**)&xp,    g_xp);
    cudaGetSymbolAddress((void**)&gx0,   g_gx0);
    cudaGetSymbolAddress((void**)&hb32,  g_hb32);
    cudaGetSymbolAddress((void**)&wib32, g_wib32);
    cudaGetSymbolAddress((void**)&whb32, g_whb32);
    cudaGetSymbolAddress((void**)&owb32, g_owb32);

    cudaFuncSetAttribute(cell_diag_kernel, cudaFuncAttributeMaxDynamicSharedMemorySize, SM_BYTES);
    cudaFuncSetAttribute(out_gemm_kernel, cudaFuncAttributeMaxDynamicSharedMemorySize, OSM_BYTES);

    // ---- prelude ----
    zero2_kernel<<<2048, 256>>>((float*)hb32, LL * BB * HH, cb, LL * BB * HH);
    cvt_all_kernel<<<1024, 256>>>(wih, whh, ow, wib32, whb32, owb32);
    gemm_bias_kernel<false><<<dim3(HH / 64, BB / 64), 256>>>(x, lw, lb, xp, BB, HH, LATENT, HH);
    gemm_bias_kernel<false><<<dim3(G4 / 64, BB / 64), 256>>>(xp, wih, bih, gx0, BB, G4, HH, G4);

    // ---- wavefront over diagonals k = l + t ----
    for (int k = 0; k < TT + LL - 1; ++k) {
        int lmin = k - (TT - 1); if (lmin < 0) lmin = 0;
        int lmax = k;            if (lmax > LL - 1) lmax = LL - 1;
        dim3 grid(4, 64, (unsigned)(lmax - lmin + 1));
        cell_diag_kernel<<<grid, 256, SM_BYTES>>>(k, lmin, bih, bhh);
    }

    // ---- bf16 mma output GEMM ----
    out_gemm_kernel<<<(BB * TT) / 128, 256, OSM_BYTES>>>(ob, out);
}

// round 16
// speedup vs baseline: 1.2476x; 1.0159x over previous
#include <cuda_runtime.h>
#include <cuda_bf16.h>
#include <math.h>
#include <stdint.h>

#define BB     4096
#define LATENT 128
#define HH     256
#define G4     1024   // 4*HH
#define OUTN   88
#define TT     64
#define LL     5

// ---------------- static device scratch (no allocations allowed) -------------
__device__ float    g_c[LL * BB * HH];
__device__ float    g_xp[BB * HH];
__device__ float    g_gx0[BB * G4];              // layer-0 input gates (const over t)
__device__ uint32_t g_ys32[BB * TT * HH / 2];    // [B][T][H] bf16 pairs
__device__ uint32_t g_hb32[LL * 2 * BB * HH / 2];   // h state, bf16 pairs, parity buffered
__device__ uint32_t g_wib32[LL * G4 * HH / 2];      // wih in bf16 pairs
__device__ uint32_t g_whb32[LL * G4 * HH / 2];      // whh in bf16 pairs
__device__ uint32_t g_owb32[OUTN * HH / 2];         // out_w in bf16 pairs
__device__ int      g_flags[LL * TT * 64];          // per (cell, m-block) completion (0..4)

#define WIH_W (LL * G4 * HH / 2)
#define OW_W  (OUTN * HH / 2)

// ---------------------------------------------------------------------------
__global__ void zero3_kernel(float* __restrict__ p1, int n1, float* __restrict__ p2, int n2,
                             int* __restrict__ p3, int n3) {
    int i = blockIdx.x * blockDim.x + threadIdx.x;
    int stride = gridDim.x * blockDim.x;
    for (; i < n1 + n2 + n3; i += stride) {
        if (i < n1) p1[i] = 0.0f;
        else if (i < n1 + n2) p2[i - n1] = 0.0f;
        else p3[i - n1 - n2] = 0;
    }
}

__device__ __forceinline__ uint32_t packbf(const float* src) {
    uint32_t lo = (uint32_t)__bfloat16_as_ushort(__float2bfloat16_rn(src[0]));
    uint32_t hi = (uint32_t)__bfloat16_as_ushort(__float2bfloat16_rn(src[1]));
    return lo | (hi << 16);
}
__global__ void cvt_all_kernel(const float* __restrict__ wih, const float* __restrict__ whh,
                               const float* __restrict__ ow,
                               uint32_t* __restrict__ wib, uint32_t* __restrict__ whb,
                               uint32_t* __restrict__ owb) {
    int i = blockIdx.x * blockDim.x + threadIdx.x;
    int stride = gridDim.x * blockDim.x;
    const int total = 2 * WIH_W + OW_W;
    for (; i < total; i += stride) {
        if (i < WIH_W)               wib[i] = packbf(wih + 2 * i);
        else if (i < 2 * WIH_W)      whb[i - WIH_W] = packbf(whh + 2 * (i - WIH_W));
        else                         owb[i - 2 * WIH_W] = packbf(ow + 2 * (i - 2 * WIH_W));
    }
}

__device__ __forceinline__ float sigf(float x) { return 1.0f / (1.0f + __expf(-x)); }
__device__ __forceinline__ float tanh_fast(float x) {
    float t = __expf(-2.0f * fabsf(x));
    float r = (1.0f - t) / (1.0f + t);
    return copysignf(r, x);
}
__device__ __forceinline__ void mma16(float* d, const uint32_t* a, uint32_t b0, uint32_t b1) {
    asm volatile(
        "mma.sync.aligned.m16n8k16.row.col.f32.bf16.bf16.f32 "
        "{%0,%1,%2,%3},{%4,%5,%6,%7},{%8,%9},{%0,%1,%2,%3};"
        : "+f"(d[0]), "+f"(d[1]), "+f"(d[2]), "+f"(d[3])
        : "r"(a[0]), "r"(a[1]), "r"(a[2]), "r"(a[3]), "r"(b0), "r"(b1));
}
__device__ __forceinline__ void ldm4(uint32_t* r, uint32_t addr) {
    asm volatile("ldmatrix.sync.aligned.m8n8.x4.shared.b16 {%0,%1,%2,%3}, [%4];"
                 : "=r"(r[0]), "=r"(r[1]), "=r"(r[2]), "=r"(r[3]) : "r"(addr));
}
__device__ __forceinline__ uint32_t smem_u32(const void* p) {
    uint32_t a;
    asm("{ .reg .u64 t; cvta.to.shared.u64 t, %1; cvt.u32.u64 %0, t; }" : "=r"(a) : "l"(p));
    return a;
}
__device__ __forceinline__ void cpasync16(uint32_t dst, const void* src) {
    asm volatile("cp.async.cg.shared.global [%0], [%1], 16;" :: "r"(dst), "l"(src) : "memory");
}
#define CP_COMMIT() asm volatile("cp.async.commit_group;" ::: "memory")
#define CP_WAIT1()  asm volatile("cp.async.wait_group 1;" ::: "memory")
#define CP_WAIT0()  asm volatile("cp.async.wait_group 0;" ::: "memory")

__device__ __forceinline__ void spin_flag(const int* p) {
    int v;
    for (;;) {
        asm volatile("ld.acquire.gpu.global.b32 %0, [%1];" : "=r"(v) : "l"(p) : "memory");
        if (v >= 4) return;
        __nanosleep(64);
    }
}
__device__ __forceinline__ void bump_flag(int* p) {
    asm volatile("red.release.gpu.global.add.s32 [%0], %1;" :: "l"(p), "r"(1) : "memory");
}
__device__ __forceinline__ float ldcg_f(const float* p) {
    float v;
    asm volatile("ld.global.cg.f32 %0, [%1];" : "=f"(v) : "l"(p));
    return v;
}

// ---------------------------------------------------------------------------
// MEGA-LAUNCH wavefront bf16 mma.sync LSTM: ALL 320 cells in one kernel.
// grid (4, 64, 320): z = cell index in diagonal order (dispatch order == dep
// order -> spin-waits deadlock-free), y = batch m-block, x = gate n-block.
// One tile per CTA; 2 CTAs/SM; per-(cell,m-block) flags count n-tiles to 4.
// Deps of (l,t): (l-1,t), (l,t-1), (l+1,t-2) -- all on diagonal k-1.
// Tile body identical to R15 (64 batch x 256 gate-cols, 8 warps 2m x 4n,
// m16n8k16 + ldmatrix.x4, KT=64, double-buffered cp.async).
// ---------------------------------------------------------------------------
#define KT          64
#define RSW         36                 // row stride in words (32 data + 4 pad)
#define AROWS       64
#define BROWS       256
#define STAGE_WORDS ((AROWS + BROWS) * RSW)   // 11520 words = 46080 B
#define AOFFW       0
#define BOFFW       (AROWS * RSW)      // 2304
#define GSTRIDE     258                // epilogue gate buffer row stride (floats)
#define SM_WORDS    (2 * STAGE_WORDS)  // 23040 words = 92160 B (> 64*258=16512)
#define SM_BYTES    (SM_WORDS * 4)

__global__ __launch_bounds__(256, 2) void cell_mega_kernel(
    const float* __restrict__ bih_g, const float* __restrict__ bhh_g)
{
    extern __shared__ uint32_t sm[];
    const uint32_t sbase = smem_u32(sm);
    const int tid = threadIdx.x;
    const int wid = tid >> 5, lane = tid & 31;
    const int grp = lane >> 2, tig = lane & 3;
    const int wm = wid & 1, wn = wid >> 1;
    const int m0 = blockIdx.y * 64;
    const int n0 = blockIdx.x * 64;

    const int q = lane >> 3, rlane = lane & 7;
    const int ldm_row = rlane + (q & 1) * 8;
    const int ldm_colw = (q >> 1) * 4;

    // ---- decode z -> (k, l, t) in diagonal order ----
    int l = 0, t = 0;
    {
        int rem = blockIdx.z;
        for (int k = 0; k < TT + LL - 1; k++) {
            int lmin = k - (TT - 1); if (lmin < 0) lmin = 0;
            int lmax = k;            if (lmax > LL - 1) lmax = LL - 1;
            int cnt = lmax - lmin + 1;
            if (rem < cnt) { l = lmin + rem; t = k - l; break; }
            rem -= cnt;
        }
    }

    // ---- wait for producers (all on previous diagonal) ----
    if (tid == 0) {
        if (l > 0)                spin_flag(&g_flags[((l - 1) * TT + t) * 64 + blockIdx.y]);
        if (t > 0)                spin_flag(&g_flags[(l * TT + (t - 1)) * 64 + blockIdx.y]);
        if (l < LL - 1 && t >= 2) spin_flag(&g_flags[((l + 1) * TT + (t - 2)) * 64 + blockIdx.y]);
    }
    __syncthreads();

    // ---- derive operands ----
    const size_t lsz = (size_t)BB * HH;
    const __nv_bfloat16* hb = reinterpret_cast<const __nv_bfloat16*>(g_hb32);
    __nv_bfloat16* hbw = reinterpret_cast<__nv_bfloat16*>(g_hb32);
    const __nv_bfloat16* wib = reinterpret_cast<const __nv_bfloat16*>(g_wib32);
    const __nv_bfloat16* whb = reinterpret_cast<const __nv_bfloat16*>(g_whb32);

    const __nv_bfloat16* h_prev = hb + (size_t)(l * 2 + ((t + 1) & 1)) * lsz;
    __nv_bfloat16*       h_o    = hbw + (size_t)(l * 2 + (t & 1)) * lsz;
    float*               cst    = g_c + (size_t)l * lsz;
    uint16_t*            ys     = (l == LL - 1)
        ? (reinterpret_cast<uint16_t*>(g_ys32) + (size_t)t * HH) : nullptr;

    const __nv_bfloat16 *A0, *W0, *A1, *W1;
    const float *bih, *gx0;
    int nst;
    const float* bhh = bhh_g + l * G4;
    if (l == 0) {
        A0 = h_prev; W0 = whb; A1 = nullptr; W1 = nullptr;
        nst = 4; bih = nullptr; gx0 = g_gx0;
    } else {
        A0 = hb + (size_t)((l - 1) * 2 + (t & 1)) * lsz;
        W0 = wib + (size_t)l * G4 * HH;
        A1 = h_prev;
        W1 = whb + (size_t)l * G4 * HH;
        nst = 8; bih = bih_g + l * G4; gx0 = nullptr;
    }
    const int half = 4;

    float acc[2][8][4] = {};

    auto load_stage = [&](int s, int buf) {
        const __nv_bfloat16* A = A0; const __nv_bfloat16* W = W0; int kt = s * KT;
        if (s >= half) { A = A1; W = W1; kt = (s - half) * KT; }
        const uint32_t base = sbase + (uint32_t)buf * (STAGE_WORDS * 4);
#pragma unroll
        for (int i = 0; i < 2; i++) {
            int c = i * 256 + tid;
            int r = c >> 3, sub = c & 7;
            cpasync16(base + (AOFFW + r * RSW + sub * 4) * 4,
                      A + (size_t)(m0 + r) * HH + kt + sub * 8);
        }
#pragma unroll
        for (int i = 0; i < 8; i++) {
            int c = i * 256 + tid;
            int r = c >> 3, sub = c & 7;
            int wrow = (r >> 6) * HH + n0 + (r & 63);
            cpasync16(base + (BOFFW + r * RSW + sub * 4) * 4,
                      W + (size_t)wrow * HH + kt + sub * 8);
        }
    };

    auto compute = [&](int buf) {
        const uint32_t sa = sbase + (uint32_t)buf * (STAGE_WORDS * 4) + AOFFW * 4;
        const uint32_t sb = sbase + (uint32_t)buf * (STAGE_WORDS * 4) + BOFFW * 4;
#pragma unroll
        for (int kk = 0; kk < 4; kk++) {
            const int k0 = kk * 8;
            uint32_t af[2][4];
#pragma unroll
            for (int mt = 0; mt < 2; mt++) {
                int ra = wm * 32 + mt * 16;
                ldm4(af[mt], sa + ((ra + ldm_row) * RSW + k0 + ldm_colw) * 4);
            }
            uint32_t bf[8][2];
#pragma unroll
            for (int ntp = 0; ntp < 4; ntp++) {
                int rb = wn * 64 + ntp * 16;
                uint32_t r4[4];
                ldm4(r4, sb + ((rb + ldm_row) * RSW + k0 + ldm_colw) * 4);
                bf[2 * ntp][0] = r4[0]; bf[2 * ntp + 1][0] = r4[1];
                bf[2 * ntp][1] = r4[2]; bf[2 * ntp + 1][1] = r4[3];
            }
#pragma unroll
            for (int nt = 0; nt < 8; nt++)
#pragma unroll
                for (int mt = 0; mt < 2; mt++)
                    mma16(acc[mt][nt], af[mt], bf[nt][0], bf[nt][1]);
        }
    };

    // ---- double-buffer pipeline, one barrier per stage ----
    load_stage(0, 0); CP_COMMIT();
    for (int s = 0; s < nst; s++) {
        CP_WAIT0();
        __syncthreads();
        if (s + 1 < nst) { load_stage(s + 1, (s + 1) & 1); CP_COMMIT(); }
        compute(s & 1);
    }
    __syncthreads();

    // ---- gate pre-activations to smem ----
    float* smf = reinterpret_cast<float*>(sm);
#pragma unroll
    for (int mt = 0; mt < 2; mt++) {
#pragma unroll
        for (int nt = 0; nt < 8; nt++) {
            int row = wm * 32 + mt * 16 + grp;
            int col = wn * 64 + nt * 8 + 2 * tig;
            *reinterpret_cast<float2*>(&smf[row * GSTRIDE + col]) =
                make_float2(acc[mt][nt][0], acc[mt][nt][1]);
            *reinterpret_cast<float2*>(&smf[(row + 8) * GSTRIDE + col]) =
                make_float2(acc[mt][nt][2], acc[mt][nt][3]);
        }
    }
    __syncthreads();

    // ---- epilogue: LSTM cell, coalesced global I/O ----
    const int u = tid & 63;
    const int n = n0 + u;
    const int bloc0 = (tid >> 6) * 16;

    float bsum[4];
#pragma unroll
    for (int gg = 0; gg < 4; gg++) {
        float v = bhh[gg * HH + n];
        if (bih) v += bih[gg * HH + n];
        bsum[gg] = v;
    }

    uint16_t* h_o16 = reinterpret_cast<uint16_t*>(h_o);
    for (int i = 0; i < 16; i++) {
        const int bl = bloc0 + i;
        const int gb = m0 + bl;
        float pre[4];
#pragma unroll
        for (int gg = 0; gg < 4; gg++)
            pre[gg] = smf[bl * GSTRIDE + gg * 64 + u] + bsum[gg];
        if (gx0) {
#pragma unroll
            for (int gg = 0; gg < 4; gg++)
                pre[gg] += gx0[(size_t)gb * G4 + gg * HH + n];
        }
        float co = ldcg_f(&cst[(size_t)gb * HH + n]);   // L2 load: cross-CTA coherent
        float iv = sigf(pre[0]);
        float fv = sigf(pre[1]);
        float gv = tanh_fast(pre[2]);
        float ov = sigf(pre[3]);
        float cn = fv * co + iv * gv;
        float hn = ov * tanh_fast(cn);
        cst[(size_t)gb * HH + n] = cn;
        uint16_t hb16 = __bfloat16_as_ushort(__float2bfloat16_rn(hn));
        h_o16[(size_t)gb * HH + n] = hb16;
        if (ys) ys[(size_t)gb * (TT * HH) + n] = hb16;
    }

    // ---- publish ----
    __threadfence();
    __syncthreads();
    if (tid == 0) bump_flag(&g_flags[(l * TT + t) * 64 + blockIdx.y]);
}

// ---------------------------------------------------------------------------
// bf16 mma output GEMM: out = sigmoid(ys @ ow.T + ob), M=BB*TT, N=88, K=256.
// ---------------------------------------------------------------------------
#define OKT    128
#define ORSW   68
#define OAR    128
#define OBR    96
#define OSTW   ((OAR + OBR) * ORSW)
#define OSM_BYTES (2 * OSTW * 4)

__global__ __launch_bounds__(256, 1) void out_gemm_kernel(
    const float* __restrict__ bias, float* __restrict__ out)
{
    extern __shared__ uint32_t sm[];
    const uint32_t sbase = smem_u32(sm);
    const int tid = threadIdx.x;
    const int wid = tid >> 5, lane = tid & 31;
    const int grp = lane >> 2, tig = lane & 3;
    const int wm = wid & 3, wn = wid >> 2;
    const int m0 = blockIdx.x * 128;

    const int q = lane >> 3, rlane = lane & 7;
    const int ldm_row = rlane + (q & 1) * 8;
    const int ldm_colw = (q >> 1) * 4;

    const __nv_bfloat16* A = reinterpret_cast<const __nv_bfloat16*>(g_ys32);
    const __nv_bfloat16* W = reinterpret_cast<const __nv_bfloat16*>(g_owb32);

    float acc[2][6][4] = {};

    auto load_stage = [&](int s, int buf) {
        const int kt = s * OKT;
        const uint32_t base = sbase + (uint32_t)buf * (OSTW * 4);
#pragma unroll
        for (int i = 0; i < 8; i++) {
            int c = i * 256 + tid;
            int r = c >> 4, sub = c & 15;
            cpasync16(base + (r * ORSW + sub * 4) * 4,
                      A + (size_t)(m0 + r) * HH + kt + sub * 8);
        }
#pragma unroll
        for (int i = 0; i < 6; i++) {
            int c = i * 256 + tid;
            int r = c >> 4, sub = c & 15;
            uint32_t dst = base + ((OAR + r) * ORSW + sub * 4) * 4;
            if (r < OUTN) {
                cpasync16(dst, W + (size_t)r * HH + kt + sub * 8);
            } else {
                *reinterpret_cast<uint4*>(
                    reinterpret_cast<char*>(sm) + (dst - sbase)) = make_uint4(0, 0, 0, 0);
            }
        }
    };

    auto compute = [&](int buf) {
        const uint32_t sa = sbase + (uint32_t)buf * (OSTW * 4);
        const uint32_t sb = sa + OAR * ORSW * 4;
#pragma unroll
        for (int kk = 0; kk < 8; kk++) {
            const int k0 = kk * 8;
            uint32_t af[2][4];
#pragma unroll
            for (int mt = 0; mt < 2; mt++) {
                int ra = wm * 32 + mt * 16;
                ldm4(af[mt], sa + ((ra + ldm_row) * ORSW + k0 + ldm_colw) * 4);
            }
            uint32_t bf[6][2];
#pragma unroll
            for (int ntp = 0; ntp < 3; ntp++) {
                int rb = wn * 48 + ntp * 16;
                uint32_t r4[4];
                ldm4(r4, sb + ((rb + ldm_row) * ORSW + k0 + ldm_colw) * 4);
                bf[2 * ntp][0] = r4[0]; bf[2 * ntp + 1][0] = r4[1];
                bf[2 * ntp][1] = r4[2]; bf[2 * ntp + 1][1] = r4[3];
            }
#pragma unroll
            for (int nt = 0; nt < 6; nt++)
#pragma unroll
                for (int mt = 0; mt < 2; mt++)
                    mma16(acc[mt][nt], af[mt], bf[nt][0], bf[nt][1]);
        }
    };

    load_stage(0, 0); CP_COMMIT();
    load_stage(1, 1); CP_COMMIT();
    CP_WAIT1(); __syncthreads(); compute(0);
    CP_WAIT0(); __syncthreads(); compute(1);

#pragma unroll
    for (int mt = 0; mt < 2; mt++) {
#pragma unroll
        for (int nt = 0; nt < 6; nt++) {
            int col = wn * 48 + nt * 8 + 2 * tig;
            int row = m0 + wm * 32 + mt * 16 + grp;
            if (col < OUTN) {
                float b0 = bias[col];
                out[(size_t)row * OUTN + col]       = sigf(acc[mt][nt][0] + b0);
                out[(size_t)(row + 8) * OUTN + col] = sigf(acc[mt][nt][2] + b0);
            }
            if (col + 1 < OUTN) {
                float b1 = bias[col + 1];
                out[(size_t)row * OUTN + col + 1]       = sigf(acc[mt][nt][1] + b1);
                out[(size_t)(row + 8) * OUTN + col + 1] = sigf(acc[mt][nt][3] + b1);
            }
        }
    }
}

// ---------------------------------------------------------------------------
// SIMT GEMM (projections only)
template <bool SIG>
__global__ __launch_bounds__(256) void gemm_bias_kernel(
    const float* __restrict__ A, const float* __restrict__ Wt,
    const float* __restrict__ bias, float* __restrict__ C,
    int M, int N, int K, int ldc)
{
    __shared__ float As[2][8][64];
    __shared__ float Bs[2][8][64];
    const int tid = threadIdx.x;
    const int tx = tid & 15, ty = tid >> 4;
    const int m0 = blockIdx.y * 64, n0 = blockIdx.x * 64;
    const int lr = tid >> 2, lc = (tid & 3) * 2;

    float acc[4][4] = {};

    auto load = [&](int tile, int buf) {
        int kt = tile * 8;
        float2 a2 = *reinterpret_cast<const float2*>(A + (size_t)(m0 + lr) * K + kt + lc);
        As[buf][lc][lr] = a2.x; As[buf][lc + 1][lr] = a2.y;
        float2 b2 = make_float2(0.0f, 0.0f);
        if (n0 + lr < N)
            b2 = *reinterpret_cast<const float2*>(Wt + (size_t)(n0 + lr) * K + kt + lc);
        Bs[buf][lc][lr] = b2.x; Bs[buf][lc + 1][lr] = b2.y;
    };

    const int ntiles = K >> 3;
    load(0, 0);
    __syncthreads();
    for (int tile = 0; tile < ntiles; ++tile) {
        int cur = tile & 1;
        if (tile + 1 < ntiles) load(tile + 1, cur ^ 1);
#pragma unroll
        for (int kk = 0; kk < 8; ++kk) {
            float4 av = *reinterpret_cast<const float4*>(&As[cur][kk][ty * 4]);
            float4 bv = *reinterpret_cast<const float4*>(&Bs[cur][kk][tx * 4]);
            float a[4] = {av.x, av.y, av.z, av.w};
            float bb[4] = {bv.x, bv.y, bv.z, bv.w};
#pragma unroll
            for (int mi = 0; mi < 4; ++mi)
#pragma unroll
                for (int ni = 0; ni < 4; ++ni)
                    acc[mi][ni] += a[mi] * bb[ni];
        }
        __syncthreads();
    }

#pragma unroll
    for (int mi = 0; mi < 4; ++mi) {
        int row = m0 + ty * 4 + mi;
#pragma unroll
        for (int ni = 0; ni < 4; ++ni) {
            int nn = n0 + tx * 4 + ni;
            if (nn < N) {
                float v = acc[mi][ni] + bias[nn];
                if (SIG) v = 1.0f / (1.0f + __expf(-v));
                C[(size_t)row * ldc + nn] = v;
            }
        }
    }
}

// ---------------------------------------------------------------------------
extern "C" void kernel_launch(void* const* d_in, const int* in_sizes, int n_in,
                              void* d_out, int out_size)
{
    const float* x   = (const float*)d_in[0];
    const float* lw  = (const float*)d_in[1];
    const float* lb  = (const float*)d_in[2];
    const float* wih = (const float*)d_in[3];
    const float* whh = (const float*)d_in[4];
    const float* bih = (const float*)d_in[5];
    const float* bhh = (const float*)d_in[6];
    const float* ow  = (const float*)d_in[7];
    const float* ob  = (const float*)d_in[8];
    float* out = (float*)d_out;

    float *cb, *xp, *gx0;
    uint32_t *hb32, *wib32, *whb32, *owb32;
    int* flags;
    cudaGetSymbolAddress((void**)&cb,    g_c);
    cudaGetSymbolAddress((void**)&xp,    g_xp);
    cudaGetSymbolAddress((void**)&gx0,   g_gx0);
    cudaGetSymbolAddress((void**)&hb32,  g_hb32);
    cudaGetSymbolAddress((void**)&wib32, g_wib32);
    cudaGetSymbolAddress((void**)&whb32, g_whb32);
    cudaGetSymbolAddress((void**)&owb32, g_owb32);
    cudaGetSymbolAddress((void**)&flags, g_flags);

    cudaFuncSetAttribute(cell_mega_kernel, cudaFuncAttributeMaxDynamicSharedMemorySize, SM_BYTES);
    cudaFuncSetAttribute(out_gemm_kernel, cudaFuncAttributeMaxDynamicSharedMemorySize, OSM_BYTES);

    // ---- prelude ----
    zero3_kernel<<<2048, 256>>>((float*)hb32, LL * BB * HH, cb, LL * BB * HH,
                                flags, LL * TT * 64);
    cvt_all_kernel<<<1024, 256>>>(wih, whh, ow, wib32, whb32, owb32);
    gemm_bias_kernel<false><<<dim3(HH / 64, BB / 64), 256>>>(x, lw, lb, xp, BB, HH, LATENT, HH);
    gemm_bias_kernel<false><<<dim3(G4 / 64, BB / 64), 256>>>(xp, wih, bih, gx0, BB, G4, HH, G4);

    // ---- ALL 320 cells: one launch, dispatch-ordered fine-grained deps ----
    cell_mega_kernel<<<dim3(4, 64, LL * TT), 256, SM_BYTES>>>(bih, bhh);

    // ---- bf16 mma output GEMM ----
    out_gemm_kernel<<<(BB * TT) / 128, 256, OSM_BYTES>>>(ob, out);
}

// round 17
// speedup vs baseline: 1.2533x; 1.0045x over previous
#include <cuda_runtime.h>
#include <cuda_bf16.h>
#include <math.h>
#include <stdint.h>

#define BB     4096
#define LATENT 128
#define HH     256
#define G4     1024   // 4*HH
#define OUTN   88
#define TT     64
#define LL     5

// ---------------- static device scratch (no allocations allowed) -------------
__device__ float    g_c[LL * BB * HH];
__device__ uint32_t g_xpb[BB * HH / 2];          // xp in bf16 pairs
__device__ float    g_gx0[BB * G4];              // layer-0 input gates (const over t)
__device__ uint32_t g_ys32[BB * TT * HH / 2];    // [B][T][H] bf16 pairs
__device__ uint32_t g_hb32[LL * 2 * BB * HH / 2];   // h state, bf16 pairs, parity buffered
__device__ uint32_t g_wib32[LL * G4 * HH / 2];      // wih in bf16 pairs
__device__ uint32_t g_whb32[LL * G4 * HH / 2];      // whh in bf16 pairs
__device__ uint32_t g_owb32[OUTN * HH / 2];         // out_w in bf16 pairs
__device__ int      g_flags[LL * TT * 64];          // per (cell, m-block) completion (0..4)

#define WIH_W (LL * G4 * HH / 2)
#define OW_W  (OUTN * HH / 2)

// ---------------------------------------------------------------------------
__global__ void zero3_kernel(float* __restrict__ p1, int n1, float* __restrict__ p2, int n2,
                             int* __restrict__ p3, int n3) {
    int i = blockIdx.x * blockDim.x + threadIdx.x;
    int stride = gridDim.x * blockDim.x;
    for (; i < n1 + n2 + n3; i += stride) {
        if (i < n1) p1[i] = 0.0f;
        else if (i < n1 + n2) p2[i - n1] = 0.0f;
        else p3[i - n1 - n2] = 0;
    }
}

__device__ __forceinline__ uint32_t packbf(const float* src) {
    uint32_t lo = (uint32_t)__bfloat16_as_ushort(__float2bfloat16_rn(src[0]));
    uint32_t hi = (uint32_t)__bfloat16_as_ushort(__float2bfloat16_rn(src[1]));
    return lo | (hi << 16);
}
__device__ __forceinline__ uint32_t packbf2(float a, float b) {
    uint32_t lo = (uint32_t)__bfloat16_as_ushort(__float2bfloat16_rn(a));
    uint32_t hi = (uint32_t)__bfloat16_as_ushort(__float2bfloat16_rn(b));
    return lo | (hi << 16);
}
__global__ void cvt_all_kernel(const float* __restrict__ wih, const float* __restrict__ whh,
                               const float* __restrict__ ow,
                               uint32_t* __restrict__ wib, uint32_t* __restrict__ whb,
                               uint32_t* __restrict__ owb) {
    int i = blockIdx.x * blockDim.x + threadIdx.x;
    int stride = gridDim.x * blockDim.x;
    const int total = 2 * WIH_W + OW_W;
    for (; i < total; i += stride) {
        if (i < WIH_W)               wib[i] = packbf(wih + 2 * i);
        else if (i < 2 * WIH_W)      whb[i - WIH_W] = packbf(whh + 2 * (i - WIH_W));
        else                         owb[i - 2 * WIH_W] = packbf(ow + 2 * (i - 2 * WIH_W));
    }
}

__device__ __forceinline__ float sigf(float x) { return 1.0f / (1.0f + __expf(-x)); }
__device__ __forceinline__ float tanh_fast(float x) {
    float t = __expf(-2.0f * fabsf(x));
    float r = (1.0f - t) / (1.0f + t);
    return copysignf(r, x);
}
__device__ __forceinline__ void mma16(float* d, const uint32_t* a, uint32_t b0, uint32_t b1) {
    asm volatile(
        "mma.sync.aligned.m16n8k16.row.col.f32.bf16.bf16.f32 "
        "{%0,%1,%2,%3},{%4,%5,%6,%7},{%8,%9},{%0,%1,%2,%3};"
        : "+f"(d[0]), "+f"(d[1]), "+f"(d[2]), "+f"(d[3])
        : "r"(a[0]), "r"(a[1]), "r"(a[2]), "r"(a[3]), "r"(b0), "r"(b1));
}
__device__ __forceinline__ void ldm4(uint32_t* r, uint32_t addr) {
    asm volatile("ldmatrix.sync.aligned.m8n8.x4.shared.b16 {%0,%1,%2,%3}, [%4];"
                 : "=r"(r[0]), "=r"(r[1]), "=r"(r[2]), "=r"(r[3]) : "r"(addr));
}
__device__ __forceinline__ uint32_t smem_u32(const void* p) {
    uint32_t a;
    asm("{ .reg .u64 t; cvta.to.shared.u64 t, %1; cvt.u32.u64 %0, t; }" : "=r"(a) : "l"(p));
    return a;
}
__device__ __forceinline__ void cpasync16(uint32_t dst, const void* src) {
    asm volatile("cp.async.cg.shared.global [%0], [%1], 16;" :: "r"(dst), "l"(src) : "memory");
}
#define CP_COMMIT() asm volatile("cp.async.commit_group;" ::: "memory")
#define CP_WAIT0()  asm volatile("cp.async.wait_group 0;" ::: "memory")

__device__ __forceinline__ void spin_flag(const int* p) {
    int v;
    for (;;) {
        asm volatile("ld.acquire.gpu.global.b32 %0, [%1];" : "=r"(v) : "l"(p) : "memory");
        if (v >= 4) return;
        __nanosleep(64);
    }
}
__device__ __forceinline__ void bump_flag(int* p) {
    asm volatile("red.release.gpu.global.add.s32 [%0], %1;" :: "l"(p), "r"(1) : "memory");
}
__device__ __forceinline__ float ldcg_f(const float* p) {
    float v;
    asm volatile("ld.global.cg.f32 %0, [%1];" : "=f"(v) : "l"(p));
    return v;
}

// ---------------------------------------------------------------------------
// bf16 mma GEMM for gx0: gx0 = xp(bf16) @ wih0^T(bf16) + bih0, fp32 out.
// M=4096, N=1024, K=256. CTA 128x128, 256 threads, 8 warps (4m x 2n),
// warp tile 32x64, KT=64, double-buffered.
// ---------------------------------------------------------------------------
#define XRSW  36
#define XSTW  ((128 + 128) * XRSW)    // 9216 words = 36864 B
#define XSM_BYTES (2 * XSTW * 4)      // 73728 B

__global__ __launch_bounds__(256) void gx0_mma_kernel(const float* __restrict__ bih_g)
{
    extern __shared__ uint32_t sm[];
    const uint32_t sbase = smem_u32(sm);
    const int tid = threadIdx.x;
    const int wid = tid >> 5, lane = tid & 31;
    const int grp = lane >> 2, tig = lane & 3;
    const int wm = wid & 3, wn = wid >> 2;
    const int n0 = blockIdx.x * 128;
    const int m0 = blockIdx.y * 128;

    const int q = lane >> 3, rlane = lane & 7;
    const int ldm_row = rlane + (q & 1) * 8;
    const int ldm_colw = (q >> 1) * 4;

    const __nv_bfloat16* A = reinterpret_cast<const __nv_bfloat16*>(g_xpb);
    const __nv_bfloat16* W = reinterpret_cast<const __nv_bfloat16*>(g_wib32);  // layer 0

    float acc[2][8][4] = {};

    auto load_stage = [&](int s, int buf) {
        const int kt = s * 64;
        const uint32_t base = sbase + (uint32_t)buf * (XSTW * 4);
#pragma unroll
        for (int i = 0; i < 4; i++) {
            int c = i * 256 + tid;
            int r = c >> 3, sub = c & 7;
            cpasync16(base + (r * XRSW + sub * 4) * 4,
                      A + (size_t)(m0 + r) * HH + kt + sub * 8);
        }
#pragma unroll
        for (int i = 0; i < 4; i++) {
            int c = i * 256 + tid;
            int r = c >> 3, sub = c & 7;
            cpasync16(base + ((128 + r) * XRSW + sub * 4) * 4,
                      W + (size_t)(n0 + r) * HH + kt + sub * 8);
        }
    };

    auto compute = [&](int buf) {
        const uint32_t sa = sbase + (uint32_t)buf * (XSTW * 4);
        const uint32_t sb = sa + 128 * XRSW * 4;
#pragma unroll
        for (int kk = 0; kk < 4; kk++) {
            const int k0 = kk * 8;
            uint32_t af[2][4];
#pragma unroll
            for (int mt = 0; mt < 2; mt++) {
                int ra = wm * 32 + mt * 16;
                ldm4(af[mt], sa + ((ra + ldm_row) * XRSW + k0 + ldm_colw) * 4);
            }
            uint32_t bf[8][2];
#pragma unroll
            for (int ntp = 0; ntp < 4; ntp++) {
                int rb = wn * 64 + ntp * 16;
                uint32_t r4[4];
                ldm4(r4, sb + ((rb + ldm_row) * XRSW + k0 + ldm_colw) * 4);
                bf[2 * ntp][0] = r4[0]; bf[2 * ntp + 1][0] = r4[1];
                bf[2 * ntp][1] = r4[2]; bf[2 * ntp + 1][1] = r4[3];
            }
#pragma unroll
            for (int nt = 0; nt < 8; nt++)
#pragma unroll
                for (int mt = 0; mt < 2; mt++)
                    mma16(acc[mt][nt], af[mt], bf[nt][0], bf[nt][1]);
        }
    };

    load_stage(0, 0); CP_COMMIT();
    for (int s = 0; s < 4; s++) {
        CP_WAIT0();
        __syncthreads();
        if (s + 1 < 4) { load_stage(s + 1, (s + 1) & 1); CP_COMMIT(); }
        compute(s & 1);
    }

#pragma unroll
    for (int mt = 0; mt < 2; mt++) {
#pragma unroll
        for (int nt = 0; nt < 8; nt++) {
            int col = n0 + wn * 64 + nt * 8 + 2 * tig;
            int row = m0 + wm * 32 + mt * 16 + grp;
            float b0 = bih_g[col], b1 = bih_g[col + 1];
            *reinterpret_cast<float2*>(&g_gx0[(size_t)row * G4 + col]) =
                make_float2(acc[mt][nt][0] + b0, acc[mt][nt][1] + b1);
            *reinterpret_cast<float2*>(&g_gx0[(size_t)(row + 8) * G4 + col]) =
                make_float2(acc[mt][nt][2] + b0, acc[mt][nt][3] + b1);
        }
    }
}

// ---------------------------------------------------------------------------
// MEGA-LAUNCH: 320 LSTM cells + output GEMM tiles in one kernel.
// z in [0,320): cell (diagonal order). z in [320,328): out tiles,
// id = (z-320)*256 + y*4 + x = t*32 + bblk; deps on top-layer flags of t.
// Cell tile body identical to R16 best.
// ---------------------------------------------------------------------------
#define KT          64
#define RSW         36
#define AROWS       64
#define BROWS       256
#define STAGE_WORDS ((AROWS + BROWS) * RSW)   // 11520 words = 46080 B
#define AOFFW       0
#define BOFFW       (AROWS * RSW)
#define GSTRIDE     258
#define SM_WORDS    (2 * STAGE_WORDS)  // 92160 B
#define SM_BYTES    (SM_WORDS * 4)
#define ORSW        68                 // out tile: 64 data words + 4 pad
#define ZCELLS      (LL * TT)

__global__ __launch_bounds__(256, 2) void cell_mega_kernel(
    const float* __restrict__ bih_g, const float* __restrict__ bhh_g,
    const float* __restrict__ ob, float* __restrict__ out)
{
    extern __shared__ uint32_t sm[];
    const uint32_t sbase = smem_u32(sm);
    const int tid = threadIdx.x;
    const int wid = tid >> 5, lane = tid & 31;
    const int grp = lane >> 2, tig = lane & 3;

    const int q = lane >> 3, rlane = lane & 7;
    const int ldm_row = rlane + (q & 1) * 8;
    const int ldm_colw = (q >> 1) * 4;

    if (blockIdx.z >= ZCELLS) {
        // =================== OUTPUT GEMM TILE ===================
        // out = sigmoid(ys @ ow^T + ob); tile = (t, 128-batch block).
        const int id = (blockIdx.z - ZCELLS) * 256 + blockIdx.y * 4 + blockIdx.x;
        const int t = id >> 5, bblk = id & 31;
        const int wm = wid & 3, wn = wid >> 2;

        if (tid == 0) {
            spin_flag(&g_flags[((LL - 1) * TT + t) * 64 + bblk * 2]);
            spin_flag(&g_flags[((LL - 1) * TT + t) * 64 + bblk * 2 + 1]);
        }
        __syncthreads();

        const __nv_bfloat16* A = reinterpret_cast<const __nv_bfloat16*>(g_ys32);
        const __nv_bfloat16* W = reinterpret_cast<const __nv_bfloat16*>(g_owb32);
        float acc[2][6][4] = {};

        for (int s = 0; s < 2; s++) {
            const int kt = s * 128;
            // A: 128 batch-rows x 128 k
#pragma unroll
            for (int i = 0; i < 8; i++) {
                int c = i * 256 + tid;
                int r = c >> 4, sub = c & 15;
                int b = bblk * 128 + r;
                cpasync16(sbase + (r * ORSW + sub * 4) * 4,
                          A + ((size_t)b * TT + t) * HH + kt + sub * 8);
            }
            // B: 96 rows (88 real + 8 zero)
#pragma unroll
            for (int i = 0; i < 6; i++) {
                int c = i * 256 + tid;
                int r = c >> 4, sub = c & 15;
                if (r < OUTN) {
                    cpasync16(sbase + ((128 + r) * ORSW + sub * 4) * 4,
                              W + (size_t)r * HH + kt + sub * 8);
                } else {
                    *reinterpret_cast<uint4*>(&sm[(128 + r) * ORSW + sub * 4]) =
                        make_uint4(0, 0, 0, 0);
                }
            }
            CP_COMMIT();
            CP_WAIT0();
            __syncthreads();
            const uint32_t sa = sbase;
            const uint32_t sb = sbase + 128 * ORSW * 4;
#pragma unroll
            for (int kk = 0; kk < 8; kk++) {
                const int k0 = kk * 8;
                uint32_t af[2][4];
#pragma unroll
                for (int mt = 0; mt < 2; mt++) {
                    int ra = wm * 32 + mt * 16;
                    ldm4(af[mt], sa + ((ra + ldm_row) * ORSW + k0 + ldm_colw) * 4);
                }
                uint32_t bf[6][2];
#pragma unroll
                for (int ntp = 0; ntp < 3; ntp++) {
                    int rb = wn * 48 + ntp * 16;
                    uint32_t r4[4];
                    ldm4(r4, sb + ((rb + ldm_row) * ORSW + k0 + ldm_colw) * 4);
                    bf[2 * ntp][0] = r4[0]; bf[2 * ntp + 1][0] = r4[1];
                    bf[2 * ntp][1] = r4[2]; bf[2 * ntp + 1][1] = r4[3];
                }
#pragma unroll
                for (int nt = 0; nt < 6; nt++)
#pragma unroll
                    for (int mt = 0; mt < 2; mt++)
                        mma16(acc[mt][nt], af[mt], bf[nt][0], bf[nt][1]);
            }
            __syncthreads();   // before next stage overwrites the buffer
        }

#pragma unroll
        for (int mt = 0; mt < 2; mt++) {
#pragma unroll
            for (int nt = 0; nt < 6; nt++) {
                int col = wn * 48 + nt * 8 + 2 * tig;
                int rloc = wm * 32 + mt * 16 + grp;
                size_t row  = ((size_t)(bblk * 128 + rloc)) * TT + t;
                size_t row8 = ((size_t)(bblk * 128 + rloc + 8)) * TT + t;
                if (col < OUTN) {
                    float b0 = ob[col];
                    out[row * OUTN + col]  = sigf(acc[mt][nt][0] + b0);
                    out[row8 * OUTN + col] = sigf(acc[mt][nt][2] + b0);
                }
                if (col + 1 < OUTN) {
                    float b1 = ob[col + 1];
                    out[row * OUTN + col + 1]  = sigf(acc[mt][nt][1] + b1);
                    out[row8 * OUTN + col + 1] = sigf(acc[mt][nt][3] + b1);
                }
            }
        }
        return;
    }

    // =================== LSTM CELL TILE (R16 body, unchanged) ===================
    const int wm = wid & 1, wn = wid >> 1;
    const int m0 = blockIdx.y * 64;
    const int n0 = blockIdx.x * 64;

    int l = 0, t = 0;
    {
        int rem = blockIdx.z;
        for (int k = 0; k < TT + LL - 1; k++) {
            int lmin = k - (TT - 1); if (lmin < 0) lmin = 0;
            int lmax = k;            if (lmax > LL - 1) lmax = LL - 1;
            int cnt = lmax - lmin + 1;
            if (rem < cnt) { l = lmin + rem; t = k - l; break; }
            rem -= cnt;
        }
    }

    if (tid == 0) {
        if (l > 0)                spin_flag(&g_flags[((l - 1) * TT + t) * 64 + blockIdx.y]);
        if (t > 0)                spin_flag(&g_flags[(l * TT + (t - 1)) * 64 + blockIdx.y]);
        if (l < LL - 1 && t >= 2) spin_flag(&g_flags[((l + 1) * TT + (t - 2)) * 64 + blockIdx.y]);
    }
    __syncthreads();

    const size_t lsz = (size_t)BB * HH;
    const __nv_bfloat16* hb = reinterpret_cast<const __nv_bfloat16*>(g_hb32);
    __nv_bfloat16* hbw = reinterpret_cast<__nv_bfloat16*>(g_hb32);
    const __nv_bfloat16* wib = reinterpret_cast<const __nv_bfloat16*>(g_wib32);
    const __nv_bfloat16* whb = reinterpret_cast<const __nv_bfloat16*>(g_whb32);

    const __nv_bfloat16* h_prev = hb + (size_t)(l * 2 + ((t + 1) & 1)) * lsz;
    __nv_bfloat16*       h_o    = hbw + (size_t)(l * 2 + (t & 1)) * lsz;
    float*               cst    = g_c + (size_t)l * lsz;
    uint16_t*            ys     = (l == LL - 1)
        ? (reinterpret_cast<uint16_t*>(g_ys32) + (size_t)t * HH) : nullptr;

    const __nv_bfloat16 *A0, *W0, *A1, *W1;
    const float *bih, *gx0;
    int nst;
    const float* bhh = bhh_g + l * G4;
    if (l == 0) {
        A0 = h_prev; W0 = whb; A1 = nullptr; W1 = nullptr;
        nst = 4; bih = nullptr; gx0 = g_gx0;
    } else {
        A0 = hb + (size_t)((l - 1) * 2 + (t & 1)) * lsz;
        W0 = wib + (size_t)l * G4 * HH;
        A1 = h_prev;
        W1 = whb + (size_t)l * G4 * HH;
        nst = 8; bih = bih_g + l * G4; gx0 = nullptr;
    }
    const int half = 4;

    float acc[2][8][4] = {};

    auto load_stage = [&](int s, int buf) {
        const __nv_bfloat16* A = A0; const __nv_bfloat16* W = W0; int kt = s * KT;
        if (s >= half) { A = A1; W = W1; kt = (s - half) * KT; }
        const uint32_t base = sbase + (uint32_t)buf * (STAGE_WORDS * 4);
#pragma unroll
        for (int i = 0; i < 2; i++) {
            int c = i * 256 + tid;
            int r = c >> 3, sub = c & 7;
            cpasync16(base + (AOFFW + r * RSW + sub * 4) * 4,
                      A + (size_t)(m0 + r) * HH + kt + sub * 8);
        }
#pragma unroll
        for (int i = 0; i < 8; i++) {
            int c = i * 256 + tid;
            int r = c >> 3, sub = c & 7;
            int wrow = (r >> 6) * HH + n0 + (r & 63);
            cpasync16(base + (BOFFW + r * RSW + sub * 4) * 4,
                      W + (size_t)wrow * HH + kt + sub * 8);
        }
    };

    auto compute = [&](int buf) {
        const uint32_t sa = sbase + (uint32_t)buf * (STAGE_WORDS * 4) + AOFFW * 4;
        const uint32_t sb = sbase + (uint32_t)buf * (STAGE_WORDS * 4) + BOFFW * 4;
#pragma unroll
        for (int kk = 0; kk < 4; kk++) {
            const int k0 = kk * 8;
            uint32_t af[2][4];
#pragma unroll
            for (int mt = 0; mt < 2; mt++) {
                int ra = wm * 32 + mt * 16;
                ldm4(af[mt], sa + ((ra + ldm_row) * RSW + k0 + ldm_colw) * 4);
            }
            uint32_t bf[8][2];
#pragma unroll
            for (int ntp = 0; ntp < 4; ntp++) {
                int rb = wn * 64 + ntp * 16;
                uint32_t r4[4];
                ldm4(r4, sb + ((rb + ldm_row) * RSW + k0 + ldm_colw) * 4);
                bf[2 * ntp][0] = r4[0]; bf[2 * ntp + 1][0] = r4[1];
                bf[2 * ntp][1] = r4[2]; bf[2 * ntp + 1][1] = r4[3];
            }
#pragma unroll
            for (int nt = 0; nt < 8; nt++)
#pragma unroll
                for (int mt = 0; mt < 2; mt++)
                    mma16(acc[mt][nt], af[mt], bf[nt][0], bf[nt][1]);
        }
    };

    load_stage(0, 0); CP_COMMIT();
    for (int s = 0; s < nst; s++) {
        CP_WAIT0();
        __syncthreads();
        if (s + 1 < nst) { load_stage(s + 1, (s + 1) & 1); CP_COMMIT(); }
        compute(s & 1);
    }
    __syncthreads();

    float* smf = reinterpret_cast<float*>(sm);
#pragma unroll
    for (int mt = 0; mt < 2; mt++) {
#pragma unroll
        for (int nt = 0; nt < 8; nt++) {
            int row = wm * 32 + mt * 16 + grp;
            int col = wn * 64 + nt * 8 + 2 * tig;
            *reinterpret_cast<float2*>(&smf[row * GSTRIDE + col]) =
                make_float2(acc[mt][nt][0], acc[mt][nt][1]);
            *reinterpret_cast<float2*>(&smf[(row + 8) * GSTRIDE + col]) =
                make_float2(acc[mt][nt][2], acc[mt][nt][3]);
        }
    }
    __syncthreads();

    const int u = tid & 63;
    const int n = n0 + u;
    const int bloc0 = (tid >> 6) * 16;

    float bsum[4];
#pragma unroll
    for (int gg = 0; gg < 4; gg++) {
        float v = bhh[gg * HH + n];
        if (bih) v += bih[gg * HH + n];
        bsum[gg] = v;
    }

    uint16_t* h_o16 = reinterpret_cast<uint16_t*>(h_o);
    for (int i = 0; i < 16; i++) {
        const int bl = bloc0 + i;
        const int gb = m0 + bl;
        float pre[4];
#pragma unroll
        for (int gg = 0; gg < 4; gg++)
            pre[gg] = smf[bl * GSTRIDE + gg * 64 + u] + bsum[gg];
        if (gx0) {
#pragma unroll
            for (int gg = 0; gg < 4; gg++)
                pre[gg] += gx0[(size_t)gb * G4 + gg * HH + n];
        }
        float co = ldcg_f(&cst[(size_t)gb * HH + n]);
        float iv = sigf(pre[0]);
        float fv = sigf(pre[1]);
        float gv = tanh_fast(pre[2]);
        float ov = sigf(pre[3]);
        float cn = fv * co + iv * gv;
        float hn = ov * tanh_fast(cn);
        cst[(size_t)gb * HH + n] = cn;
        uint16_t hb16 = __bfloat16_as_ushort(__float2bfloat16_rn(hn));
        h_o16[(size_t)gb * HH + n] = hb16;
        if (ys) ys[(size_t)gb * (TT * HH) + n] = hb16;
    }

    __threadfence();
    __syncthreads();
    if (tid == 0) bump_flag(&g_flags[(l * TT + t) * 64 + blockIdx.y]);
}

// ---------------------------------------------------------------------------
// SIMT GEMM (xp projection), optional packed-bf16 output.
template <bool BFOUT>
__global__ __launch_bounds__(256) void gemm_bias_kernel(
    const float* __restrict__ A, const float* __restrict__ Wt,
    const float* __restrict__ bias, float* __restrict__ C,
    int M, int N, int K, int ldc)
{
    __shared__ float As[2][8][64];
    __shared__ float Bs[2][8][64];
    const int tid = threadIdx.x;
    const int tx = tid & 15, ty = tid >> 4;
    const int m0 = blockIdx.y * 64, n0 = blockIdx.x * 64;
    const int lr = tid >> 2, lc = (tid & 3) * 2;

    float acc[4][4] = {};

    auto load = [&](int tile, int buf) {
        int kt = tile * 8;
        float2 a2 = *reinterpret_cast<const float2*>(A + (size_t)(m0 + lr) * K + kt + lc);
        As[buf][lc][lr] = a2.x; As[buf][lc + 1][lr] = a2.y;
        float2 b2 = make_float2(0.0f, 0.0f);
        if (n0 + lr < N)
            b2 = *reinterpret_cast<const float2*>(Wt + (size_t)(n0 + lr) * K + kt + lc);
        Bs[buf][lc][lr] = b2.x; Bs[buf][lc + 1][lr] = b2.y;
    };

    const int ntiles = K >> 3;
    load(0, 0);
    __syncthreads();
    for (int tile = 0; tile < ntiles; ++tile) {
        int cur = tile & 1;
        if (tile + 1 < ntiles) load(tile + 1, cur ^ 1);
#pragma unroll
        for (int kk = 0; kk < 8; ++kk) {
            float4 av = *reinterpret_cast<const float4*>(&As[cur][kk][ty * 4]);
            float4 bv = *reinterpret_cast<const float4*>(&Bs[cur][kk][tx * 4]);
            float a[4] = {av.x, av.y, av.z, av.w};
            float bb[4] = {bv.x, bv.y, bv.z, bv.w};
#pragma unroll
            for (int mi = 0; mi < 4; ++mi)
#pragma unroll
                for (int ni = 0; ni < 4; ++ni)
                    acc[mi][ni] += a[mi] * bb[ni];
        }
        __syncthreads();
    }

#pragma unroll
    for (int mi = 0; mi < 4; ++mi) {
        int row = m0 + ty * 4 + mi;
        if (BFOUT) {
            uint32_t* Cb = reinterpret_cast<uint32_t*>(C);
            int nb = n0 + tx * 4;
            Cb[(size_t)row * (ldc >> 1) + (nb >> 1)] =
                packbf2(acc[mi][0] + bias[nb], acc[mi][1] + bias[nb + 1]);
            Cb[(size_t)row * (ldc >> 1) + (nb >> 1) + 1] =
                packbf2(acc[mi][2] + bias[nb + 2], acc[mi][3] + bias[nb + 3]);
        } else {
#pragma unroll
            for (int ni = 0; ni < 4; ++ni) {
                int nn = n0 + tx * 4 + ni;
                if (nn < N)
                    C[(size_t)row * ldc + nn] = acc[mi][ni] + bias[nn];
            }
        }
    }
}

// ---------------------------------------------------------------------------
extern "C" void kernel_launch(void* const* d_in, const int* in_sizes, int n_in,
                              void* d_out, int out_size)
{
    const float* x   = (const float*)d_in[0];
    const float* lw  = (const float*)d_in[1];
    const float* lb  = (const float*)d_in[2];
    const float* wih = (const float*)d_in[3];
    const float* whh = (const float*)d_in[4];
    const float* bih = (const float*)d_in[5];
    const float* bhh = (const float*)d_in[6];
    const float* ow  = (const float*)d_in[7];
    const float* ob  = (const float*)d_in[8];
    float* out = (float*)d_out;

    float *cb;
    uint32_t *hb32, *wib32, *whb32, *owb32, *xpb;
    int* flags;
    cudaGetSymbolAddress((void**)&cb,    g_c);
    cudaGetSymbolAddress((void**)&xpb,   g_xpb);
    cudaGetSymbolAddress((void**)&hb32,  g_hb32);
    cudaGetSymbolAddress((void**)&wib32, g_wib32);
    cudaGetSymbolAddress((void**)&whb32, g_whb32);
    cudaGetSymbolAddress((void**)&owb32, g_owb32);
    cudaGetSymbolAddress((void**)&flags, g_flags);

    cudaFuncSetAttribute(cell_mega_kernel, cudaFuncAttributeMaxDynamicSharedMemorySize, SM_BYTES);
    cudaFuncSetAttribute(gx0_mma_kernel, cudaFuncAttributeMaxDynamicSharedMemorySize, XSM_BYTES);

    // ---- prelude ----
    zero3_kernel<<<2048, 256>>>((float*)hb32, LL * BB * HH, cb, LL * BB * HH,
                                flags, LL * TT * 64);
    cvt_all_kernel<<<1024, 256>>>(wih, whh, ow, wib32, whb32, owb32);
    // xp (bf16) = x @ lw.T + lb
    gemm_bias_kernel<true><<<dim3(HH / 64, BB / 64), 256>>>(
        x, lw, lb, (float*)xpb, BB, HH, LATENT, HH);
    // gx0 = xp @ wih0.T + bih0 (bf16 mma, fp32 out)
    gx0_mma_kernel<<<dim3(G4 / 128, BB / 128), 256, XSM_BYTES>>>(bih);

    // ---- 320 cells + 2048 output tiles: one launch ----
    cell_mega_kernel<<<dim3(4, 64, ZCELLS + 8), 256, SM_BYTES>>>(bih, bhh, ob, out);
}